// round 6
// baseline (speedup 1.0000x reference)
#include <cuda_runtime.h>
#include <cuda_bf16.h>
#include <math.h>
#include <stdint.h>

#if !defined(__CUDA_ARCH__) || defined(__CUDA_ARCH_FEAT_SM103_ALL) || \
    defined(__CUDA_ARCH_FEAT_SM100_ALL) || defined(__CUDA_ARCH_FEAT_SM101_ALL) || \
    defined(__CUDA_ARCH_FEAT_SM110_ALL)
#define HAS_TC 1
#else
#define HAS_TC 0
#endif

#define BB 16
#define TT 2000
#define MM (BB*TT)
#define DENC 512
#define VV 1024
#define EE 256
#define PP 640
#define JJ 640

// ---------------- scratch ----------------
__device__ float g_enc[(size_t)MM * VV];
__device__ float g_pred[(size_t)MM * VV];
__device__ float g_logits[(size_t)MM * VV];
__device__ __nv_bfloat16 g_hsum[(size_t)MM * VV];
__device__ __nv_bfloat16 g_hb1[(size_t)MM * PP];
__device__ __nv_bfloat16 g_hb2[(size_t)MM * PP];
__device__ __nv_bfloat16 g_encbf[(size_t)MM * DENC];
__device__ __nv_bfloat16 g_embbf[(size_t)VV * EE];
__device__ __nv_bfloat16 g_wt[4u * 1024u * 1024u];
__device__ int2  g_ctx[MM];

#define O_ENC 0
#define O_P1  524288
#define O_P2  851968
#define O_PO  1261568
#define O_J1  1916928
#define O_J2  2572288

__device__ __forceinline__ uint32_t smem_u32(const void* p) {
    uint32_t a;
    asm("{ .reg .u64 t; cvta.to.shared.u64 t, %1; cvt.u32.u64 %0, t; }" : "=r"(a) : "l"(p));
    return a;
}
#define SWZ(b) ((b) ^ (((b) >> 3) & 0x70))

#if HAS_TC
__device__ __forceinline__ uint32_t elect1() {
    uint32_t p;
    asm volatile("{\n\t.reg .pred p;\n\telect.sync _|p, 0xFFFFFFFF;\n\tselp.b32 %0, 1, 0, p;\n\t}" : "=r"(p));
    return p;
}
__device__ __forceinline__ uint64_t make_desc(uint32_t addr) {
    return ((uint64_t)((addr >> 4) & 0x3FFF))
         | (1ull << 16) | (64ull << 32) | (1ull << 46) | (2ull << 61);
}
__device__ __forceinline__ void cp16(uint32_t s, const void* g) {
    asm volatile("cp.async.cg.shared.global [%0], [%1], 16;\n" :: "r"(s), "l"(g));
}
#define CP_COMMIT() asm volatile("cp.async.commit_group;\n" ::: "memory")

__device__ __forceinline__ void mbar_init(uint32_t a, uint32_t cnt) {
    asm volatile("mbarrier.init.shared.b64 [%0], %1;" :: "r"(a), "r"(cnt) : "memory");
}
__device__ __forceinline__ void mbar_wait(uint32_t a, uint32_t parity) {
    uint32_t done = 0;
    while (!done) {
        asm volatile("{\n\t.reg .pred p;\n\t"
            "mbarrier.try_wait.parity.acquire.cta.shared::cta.b64 p, [%1], %2, 0x989680;\n\t"
            "selp.b32 %0, 1, 0, p;\n\t}"
            : "=r"(done) : "r"(a), "r"(parity) : "memory");
    }
}
__device__ __forceinline__ void tc_alloc(uint32_t slot, uint32_t ncols) {
    asm volatile("tcgen05.alloc.cta_group::1.sync.aligned.shared::cta.b32 [%0], %1;"
                 :: "r"(slot), "r"(ncols) : "memory");
}
__device__ __forceinline__ void tc_dealloc(uint32_t tmem, uint32_t ncols) {
    asm volatile("tcgen05.dealloc.cta_group::1.sync.aligned.b32 %0, %1;" :: "r"(tmem), "r"(ncols));
}
__device__ __forceinline__ void tc_relinq() {
    asm volatile("tcgen05.relinquish_alloc_permit.cta_group::1.sync.aligned;");
}
__device__ __forceinline__ void tc_commit(uint32_t mbar) {
    asm volatile("tcgen05.commit.cta_group::1.mbarrier::arrive::one.shared::cluster.b64 [%0];"
                 :: "r"(mbar) : "memory");
}
__device__ __forceinline__ void mma_bf16_ss(uint32_t d, uint64_t ad, uint64_t bd,
                                            uint32_t idesc, uint32_t en) {
    asm volatile(
        "{\n\t.reg .pred p;\n\tsetp.ne.u32 p, %4, 0;\n\t"
        "tcgen05.mma.cta_group::1.kind::f16 [%0], %1, %2, %3, p;\n\t}"
        :: "r"(d), "l"(ad), "l"(bd), "r"(idesc), "r"(en) : "memory");
}
__device__ __forceinline__ void ldtm32(uint32_t* r, uint32_t a) {
    asm volatile(
        "tcgen05.ld.sync.aligned.32x32b.x32.b32 "
        "{%0, %1, %2, %3, %4, %5, %6, %7, %8, %9, %10, %11, %12, %13, %14, %15, "
        " %16, %17, %18, %19, %20, %21, %22, %23, %24, %25, %26, %27, %28, %29, %30, %31}, [%32];"
        : "=r"(r[0]), "=r"(r[1]), "=r"(r[2]), "=r"(r[3]), "=r"(r[4]), "=r"(r[5]), "=r"(r[6]), "=r"(r[7]),
          "=r"(r[8]), "=r"(r[9]), "=r"(r[10]), "=r"(r[11]), "=r"(r[12]), "=r"(r[13]), "=r"(r[14]), "=r"(r[15]),
          "=r"(r[16]), "=r"(r[17]), "=r"(r[18]), "=r"(r[19]), "=r"(r[20]), "=r"(r[21]), "=r"(r[22]), "=r"(r[23]),
          "=r"(r[24]), "=r"(r[25]), "=r"(r[26]), "=r"(r[27]), "=r"(r[28]), "=r"(r[29]), "=r"(r[30]), "=r"(r[31])
        : "r"(a));
}
#define TC_WAIT_LD()  asm volatile("tcgen05.wait::ld.sync.aligned;" ::: "memory")
#define TC_FENCE_AFTER()  asm volatile("tcgen05.fence::after_thread_sync;" ::: "memory")
#define TC_FENCE_BEFORE() asm volatile("tcgen05.fence::before_thread_sync;" ::: "memory")

// ---- one GEMM tile pass: C[gRow:gRow+128, ncol0:ncol0+BN] (ptrs pre-offset by ncol0)
// ASRC: 0=A[M,K] bf16; 1=gather g_embbf via g_ctx. OUTMODE: 0=fp32 Cf; 1=bf16 Ch(+tanh per ACT);
// 2=fp32 Cf + bf16 Csum=Cf+Cadd.
template<int BN, int ASRC, int ACT, int OUTMODE>
__device__ __forceinline__ void tile_pass(
    uint32_t sbase, uint32_t tmem, int call, int gRow,
    const __nv_bfloat16* __restrict__ A, const __nv_bfloat16* __restrict__ BtT,
    const float* __restrict__ bias, float* __restrict__ Cf, __nv_bfloat16* __restrict__ Ch,
    const float* __restrict__ Cadd, __nv_bfloat16* __restrict__ Csum, int K, int ldc)
{
    const int tid = threadIdx.x, wid = tid >> 5, lane = tid & 31;
    const uint32_t mb = sbase + 16 + call * 16;
    const uint32_t tile0 = (sbase + 2048 + 1023) & ~1023u;
    const int STAGE = (128 + BN) * 128;
    const int KT = K / 64;

    auto load_stage = [&](int ki, int s) {
        const int k0 = ki * 64;
        const uint32_t ab = tile0 + s * STAGE;
        const uint32_t bb = ab + 128 * 128;
        #pragma unroll
        for (int t = 0; t < 4; t++) {
            int q = tid + t * 256, r = q >> 3, cv = q & 7;
            const __nv_bfloat16* gp;
            if (ASRC == 1) {
                int2 cx = g_ctx[gRow + r];
                int idx = (k0 < 256) ? cx.x : cx.y;
                gp = g_embbf + (size_t)idx * EE + ((k0 & 255) + cv * 8);
            } else gp = A + (size_t)(gRow + r) * K + (k0 + cv * 8);
            cp16(ab + SWZ(r * 128 + cv * 16), gp);
        }
        #pragma unroll
        for (int t = 0; t < BN / 32; t++) {
            int q = tid + t * 256, r = q >> 3, cv = q & 7;
            cp16(bb + SWZ(r * 128 + cv * 16), BtT + (size_t)r * K + (k0 + cv * 8));
        }
    };

    load_stage(0, 0); CP_COMMIT();
    load_stage(1, 1); CP_COMMIT();

    constexpr int NCH = (BN + 255) / 256;
    constexpr int NC1 = (BN >= 256) ? 256 : BN;
    const uint32_t idesc = (1u << 4) | (1u << 7) | (1u << 10)
                         | ((uint32_t)(NC1 / 8) << 17) | (8u << 24);

    for (int i = 0; i < KT; i++) {
        const int s = i & 1;
        asm volatile("cp.async.wait_group 1;\n" ::: "memory");
        __syncthreads();
        if (wid == 0) {
            asm volatile("fence.proxy.async.shared::cta;" ::: "memory");
            TC_FENCE_AFTER();
            if (elect1()) {
                const uint32_t ab = tile0 + s * STAGE;
                const uint32_t bb = ab + 128 * 128;
                uint64_t ad = make_desc(ab);
                #pragma unroll
                for (int c = 0; c < NCH; c++) {
                    uint64_t bd = make_desc(bb + c * (256 * 128));
                    #pragma unroll
                    for (int kk = 0; kk < 4; kk++)
                        mma_bf16_ss(tmem + c * 256, ad + kk * 2, bd + kk * 2, idesc,
                                    (i | kk) ? 1u : 0u);
                }
                tc_commit(mb + 8 * s);
            }
        }
        if (i + 2 < KT) {
            mbar_wait(mb + 8 * s, (i / 2) & 1);
            load_stage(i + 2, s);
        }
        CP_COMMIT();
    }
    mbar_wait(mb + 8 * ((KT - 1) & 1), ((KT - 1) / 2) & 1);
    TC_FENCE_AFTER();
    __syncthreads();

    if (wid < 4) {
        const int row = gRow + wid * 32 + lane;
        float* crowf = (OUTMODE != 1) ? (Cf + (size_t)row * ldc) : nullptr;
        __nv_bfloat16* crowh = (OUTMODE == 1) ? (Ch + (size_t)row * ldc) : nullptr;
        const float* erow = (OUTMODE == 2) ? (Cadd + (size_t)row * ldc) : nullptr;
        __nv_bfloat16* srow = (OUTMODE == 2) ? (Csum + (size_t)row * ldc) : nullptr;
        #pragma unroll
        for (int c0 = 0; c0 < BN; c0 += 32) {
            uint32_t r[32];
            ldtm32(r, tmem + c0);
            TC_WAIT_LD();
            #pragma unroll
            for (int j = 0; j < 32; j += 4) {
                float4 b4 = *reinterpret_cast<const float4*>(bias + c0 + j);
                float4 o;
                o.x = __uint_as_float(r[j + 0]) + b4.x;
                o.y = __uint_as_float(r[j + 1]) + b4.y;
                o.z = __uint_as_float(r[j + 2]) + b4.z;
                o.w = __uint_as_float(r[j + 3]) + b4.w;
                if (ACT) { o.x = tanhf(o.x); o.y = tanhf(o.y); o.z = tanhf(o.z); o.w = tanhf(o.w); }
                if (OUTMODE == 1) {
                    reinterpret_cast<__nv_bfloat162*>(crowh + c0 + j)[0] = __floats2bfloat162_rn(o.x, o.y);
                    reinterpret_cast<__nv_bfloat162*>(crowh + c0 + j)[1] = __floats2bfloat162_rn(o.z, o.w);
                } else {
                    *reinterpret_cast<float4*>(crowf + c0 + j) = o;
                    if (OUTMODE == 2) {
                        float4 e4 = *reinterpret_cast<const float4*>(erow + c0 + j);
                        reinterpret_cast<__nv_bfloat162*>(srow + c0 + j)[0] = __floats2bfloat162_rn(o.x + e4.x, o.y + e4.y);
                        reinterpret_cast<__nv_bfloat162*>(srow + c0 + j)[1] = __floats2bfloat162_rn(o.z + e4.z, o.w + e4.w);
                    }
                }
            }
        }
        TC_FENCE_BEFORE();
    }
    __syncthreads();
}
#else
// ---- SIMT fallback pass (compute_103 PTX pass only; never selected at runtime)
__device__ void simt_pass(int gRow, const __nv_bfloat16* A, const __nv_bfloat16* Bt,
    const float* bias, float* Cf, __nv_bfloat16* Ch, const float* Cadd, __nv_bfloat16* Csum,
    int K, int N, int ldc, int asrc, int act)
{
    int tid = threadIdx.x;
    for (int idx = tid; idx < 128 * N; idx += 256) {
        int r = idx / N, n = idx % N;
        int row = gRow + r;
        float acc = 0.f;
        int2 cx = g_ctx[row];
        for (int k = 0; k < K; k++) {
            float a;
            if (asrc == 1) {
                int e = (k < 256) ? cx.x : cx.y;
                a = __bfloat162float(g_embbf[(size_t)e * EE + (k & 255)]);
            } else a = __bfloat162float(A[(size_t)row * K + k]);
            acc += a * __bfloat162float(Bt[(size_t)n * K + k]);
        }
        acc += bias[n];
        if (act) acc = tanhf(acc);
        if (Ch) Ch[(size_t)row * ldc + n] = __float2bfloat16(acc);
        if (Cf) Cf[(size_t)row * ldc + n] = acc;
        if (Csum) Csum[(size_t)row * ldc + n] = __float2bfloat16(acc + Cadd[(size_t)row * ldc + n]);
    }
    __syncthreads();
}
#endif

// ---------------- fused chain kernel: all 6 layers per row-block ----------------
__global__ __launch_bounds__(256) void fused_chain(
    const __nv_bfloat16* __restrict__ encbf, const __nv_bfloat16* __restrict__ wt,
    const float* __restrict__ b_enc, const float* __restrict__ b_p1,
    const float* __restrict__ b_p2, const float* __restrict__ b_po,
    const float* __restrict__ b_j1, const float* __restrict__ b_j2,
    float* __restrict__ enc, float* __restrict__ pred, float* __restrict__ logits,
    __nv_bfloat16* __restrict__ hsum, __nv_bfloat16* __restrict__ hb1,
    __nv_bfloat16* __restrict__ hb2)
{
    const int gRow = blockIdx.x * 128;
#if HAS_TC
    extern __shared__ char smem[];
    const uint32_t sbase = smem_u32(smem);
    const int tid = threadIdx.x, wid = tid >> 5;
    if (wid == 0) tc_alloc(sbase, 512);
    if (tid < 24) mbar_init(sbase + 16 + tid * 8, 1);
    __syncthreads();
    uint32_t tmem;
    asm volatile("ld.shared.b32 %0, [%1];" : "=r"(tmem) : "r"(sbase));

    // L0: enc = encbf @ Wenc + b  (fp32)
    tile_pass<512,0,0,0>(sbase,tmem,0,gRow, encbf, wt+O_ENC,                  b_enc,     enc,     nullptr, nullptr, nullptr, 512,1024);
    tile_pass<512,0,0,0>(sbase,tmem,1,gRow, encbf, wt+O_ENC+(size_t)512*512,  b_enc+512, enc+512, nullptr, nullptr, nullptr, 512,1024);
    // L1: a1 = tanh(gather @ Wp1 + b)  (bf16)
    tile_pass<512,1,1,1>(sbase,tmem,2,gRow, nullptr, wt+O_P1,                 b_p1,      nullptr, hb1,     nullptr, nullptr, 512,640);
    tile_pass<128,1,1,1>(sbase,tmem,3,gRow, nullptr, wt+O_P1+(size_t)512*512, b_p1+512,  nullptr, hb1+512, nullptr, nullptr, 512,640);
    // L2: a2 = tanh(a1 @ Wp2 + b)  (bf16)
    tile_pass<512,0,1,1>(sbase,tmem,4,gRow, hb1, wt+O_P2,                     b_p2,      nullptr, hb2,     nullptr, nullptr, 640,640);
    tile_pass<128,0,1,1>(sbase,tmem,5,gRow, hb1, wt+O_P2+(size_t)512*640,     b_p2+512,  nullptr, hb2+512, nullptr, nullptr, 640,640);
    // L3: pred = a2 @ Wpo + b (fp32); hsum = bf16(pred + enc)
    tile_pass<512,0,0,2>(sbase,tmem,6,gRow, hb2, wt+O_PO,                     b_po,      pred,     nullptr, enc,     hsum,     640,1024);
    tile_pass<512,0,0,2>(sbase,tmem,7,gRow, hb2, wt+O_PO+(size_t)512*640,     b_po+512,  pred+512, nullptr, enc+512, hsum+512, 640,1024);
    // L4: h = tanh(hsum @ Wj1 + b)  (bf16)
    tile_pass<512,0,1,1>(sbase,tmem,8,gRow, hsum, wt+O_J1,                    b_j1,      nullptr, hb1,     nullptr, nullptr, 1024,640);
    tile_pass<128,0,1,1>(sbase,tmem,9,gRow, hsum, wt+O_J1+(size_t)512*1024,   b_j1+512,  nullptr, hb1+512, nullptr, nullptr, 1024,640);
    // L5: logits = h @ Wj2 + b  (fp32)
    tile_pass<512,0,0,0>(sbase,tmem,10,gRow, hb1, wt+O_J2,                    b_j2,      logits,     nullptr, nullptr, nullptr, 640,1024);
    tile_pass<512,0,0,0>(sbase,tmem,11,gRow, hb1, wt+O_J2+(size_t)512*640,    b_j2+512,  logits+512, nullptr, nullptr, nullptr, 640,1024);

    if (wid == 0) { tc_relinq(); tc_dealloc(tmem, 512); }
#else
    simt_pass(gRow, encbf, wt+O_ENC, b_enc, enc, nullptr, nullptr, nullptr, 512, 1024, 1024, 0, 0);
    simt_pass(gRow, nullptr, wt+O_P1, b_p1, nullptr, hb1, nullptr, nullptr, 512, 640, 640, 1, 1);
    simt_pass(gRow, hb1, wt+O_P2, b_p2, nullptr, hb2, nullptr, nullptr, 640, 640, 640, 0, 1);
    simt_pass(gRow, hb2, wt+O_PO, b_po, pred, nullptr, enc, hsum, 640, 1024, 1024, 0, 0);
    simt_pass(gRow, hsum, wt+O_J1, b_j1, nullptr, hb1, nullptr, nullptr, 1024, 640, 640, 0, 1);
    simt_pass(gRow, hb1, wt+O_J2, b_j2, logits, nullptr, nullptr, nullptr, 640, 1024, 1024, 0, 0);
#endif
}

// ---------------- merged weight transpose (fp32 [K,N] -> bf16 [N,K]) ----------------
__global__ void transpose_all(
    const float* __restrict__ W0, const float* __restrict__ W1, const float* __restrict__ W2,
    const float* __restrict__ W3, const float* __restrict__ W4, const float* __restrict__ W5,
    __nv_bfloat16* __restrict__ wt)
{
    __shared__ float tile[32][33];
    const float* W; __nv_bfloat16* Wt; int K, N;
    switch (blockIdx.y) {
        case 0:  W = W0; Wt = wt + O_ENC; K = DENC; N = VV; break;
        case 1:  W = W1; Wt = wt + O_P1;  K = DENC; N = PP; break;
        case 2:  W = W2; Wt = wt + O_P2;  K = PP;   N = PP; break;
        case 3:  W = W3; Wt = wt + O_PO;  K = PP;   N = VV; break;
        case 4:  W = W4; Wt = wt + O_J1;  K = VV;   N = JJ; break;
        default: W = W5; Wt = wt + O_J2;  K = JJ;   N = VV; break;
    }
    int tn = N / 32;
    if ((int)blockIdx.x >= tn * (K / 32)) return;
    int n0 = ((int)blockIdx.x % tn) * 32, k0 = ((int)blockIdx.x / tn) * 32;
    int tx = threadIdx.x, ty = threadIdx.y;
    #pragma unroll
    for (int i = 0; i < 32; i += 8)
        tile[ty + i][tx] = W[(size_t)(k0 + ty + i) * N + n0 + tx];
    __syncthreads();
    #pragma unroll
    for (int i = 0; i < 32; i += 8)
        Wt[(size_t)(n0 + ty + i) * K + k0 + tx] = __float2bfloat16(tile[tx][ty + i]);
}

__global__ void f2bf_kernel(const float* __restrict__ s, __nv_bfloat16* __restrict__ d, int n4) {
    int i = blockIdx.x * blockDim.x + threadIdx.x;
    if (i >= n4) return;
    float4 v = reinterpret_cast<const float4*>(s)[i];
    reinterpret_cast<__nv_bfloat162*>(d)[i * 2]     = __floats2bfloat162_rn(v.x, v.y);
    reinterpret_cast<__nv_bfloat162*>(d)[i * 2 + 1] = __floats2bfloat162_rn(v.z, v.w);
}

__global__ void ctx_kernel(const int* __restrict__ targets) {
    __shared__ int pmax[2048];
    __shared__ int tot[256];
    int b = blockIdx.x;
    const int* tg = targets + (size_t)b * TT;
    int tid = threadIdx.x;
    int loc[8];
    int run = -1;
    #pragma unroll
    for (int j = 0; j < 8; ++j) {
        int t = tid * 8 + j;
        int p = (t < TT && tg[t] != 0) ? t : -1;
        run = max(run, p);
        loc[j] = run;
    }
    tot[tid] = run;
    __syncthreads();
    if (tid == 0) {
        int r = -1;
        for (int i = 0; i < 256; ++i) { int v = tot[i]; tot[i] = r; r = max(r, v); }
    }
    __syncthreads();
    int off = tot[tid];
    #pragma unroll
    for (int j = 0; j < 8; ++j) pmax[tid * 8 + j] = max(off, loc[j]);
    __syncthreads();
    for (int t = tid; t < TT; t += 256) {
        int p1 = (t >= 1) ? pmax[t - 1] : -1;
        int p2 = (t >= 2) ? pmax[t - 2] : -1;
        g_ctx[(size_t)b * TT + t] = make_int2(p1 >= 0 ? tg[p1] : 0, p2 >= 0 ? tg[p2] : 0);
    }
}

// ---------------- merged log-softmax (3 tensors) ----------------
__global__ __launch_bounds__(256) void logsoftmax3(
    const float* __restrict__ lg, const float* __restrict__ pd,
    const float* __restrict__ en, float* __restrict__ out)
{
    __shared__ float redm[8];
    __shared__ float reds[8];
    int row = blockIdx.x;
    const float* X; float* Y;
    if (blockIdx.y == 0)      { X = lg; Y = out; }
    else if (blockIdx.y == 1) { X = pd; Y = out + (size_t)MM * VV; }
    else                      { X = en; Y = out + 2 * (size_t)MM * VV; }
    int tid = threadIdx.x;
    float4 x = reinterpret_cast<const float4*>(X + (size_t)row * VV)[tid];
    float m = fmaxf(fmaxf(x.x, x.y), fmaxf(x.z, x.w));
    #pragma unroll
    for (int o = 16; o; o >>= 1) m = fmaxf(m, __shfl_xor_sync(0xffffffffu, m, o));
    if ((tid & 31) == 0) redm[tid >> 5] = m;
    __syncthreads();
    float mx = redm[0];
    #pragma unroll
    for (int i = 1; i < 8; ++i) mx = fmaxf(mx, redm[i]);
    float s = expf(x.x - mx) + expf(x.y - mx) + expf(x.z - mx) + expf(x.w - mx);
    #pragma unroll
    for (int o = 16; o; o >>= 1) s += __shfl_xor_sync(0xffffffffu, s, o);
    if ((tid & 31) == 0) reds[tid >> 5] = s;
    __syncthreads();
    float sum = 0.f;
    #pragma unroll
    for (int i = 0; i < 8; ++i) sum += reds[i];
    float lse = mx + logf(sum);
    float4 y = make_float4(x.x - lse, x.y - lse, x.z - lse, x.w - lse);
    reinterpret_cast<float4*>(Y + (size_t)row * VV)[tid] = y;
}

__global__ void lens_kernel(const int* __restrict__ flen, float* __restrict__ out) {
    int i = threadIdx.x;
    if (i < BB) out[i] = (float)flen[i];
}

// ---------------- launch ----------------
extern "C" void kernel_launch(void* const* d_in, const int* in_sizes, int n_in,
                              void* d_out, int out_size)
{
    const float* encoder_out  = (const float*)d_in[0];
    const int*   features_len = (const int*)  d_in[1];
    const int*   targets      = (const int*)  d_in[2];
    const float* W_enc = (const float*)d_in[3];
    const float* b_enc = (const float*)d_in[4];
    const float* emb   = (const float*)d_in[5];
    const float* W_p1  = (const float*)d_in[6];
    const float* b_p1  = (const float*)d_in[7];
    const float* W_p2  = (const float*)d_in[8];
    const float* b_p2  = (const float*)d_in[9];
    const float* W_po  = (const float*)d_in[10];
    const float* b_po  = (const float*)d_in[11];
    const float* W_j1  = (const float*)d_in[12];
    const float* b_j1  = (const float*)d_in[13];
    const float* W_j2  = (const float*)d_in[14];
    const float* b_j2  = (const float*)d_in[15];

    float *enc, *pred, *logits;
    __nv_bfloat16 *hsum, *hb1, *hb2, *encbf, *embbf, *wt;
    cudaGetSymbolAddress((void**)&enc,    g_enc);
    cudaGetSymbolAddress((void**)&pred,   g_pred);
    cudaGetSymbolAddress((void**)&logits, g_logits);
    cudaGetSymbolAddress((void**)&hsum,   g_hsum);
    cudaGetSymbolAddress((void**)&hb1,    g_hb1);
    cudaGetSymbolAddress((void**)&hb2,    g_hb2);
    cudaGetSymbolAddress((void**)&encbf,  g_encbf);
    cudaGetSymbolAddress((void**)&embbf,  g_embbf);
    cudaGetSymbolAddress((void**)&wt,     g_wt);

    float* out = (float*)d_out;
    float* out_lens = out + 3 * (size_t)MM * VV;

    const int SMEMSZ = 2048 + 1024 + 2 * (128 + 512) * 128;   // 166912
    cudaFuncSetAttribute(fused_chain, cudaFuncAttributeMaxDynamicSharedMemorySize, SMEMSZ);

    // launch order chosen so ncu (-s 5 -c 1) captures fused_chain (6th launch)
    ctx_kernel<<<BB, 256>>>(targets);                                             // 1
    f2bf_kernel<<<(MM * DENC / 4 + 255) / 256, 256>>>(encoder_out, encbf, MM * DENC / 4);  // 2
    f2bf_kernel<<<(VV * EE / 4 + 255) / 256, 256>>>(emb, embbf, VV * EE / 4);     // 3
    transpose_all<<<dim3(640, 6), dim3(32, 8)>>>(W_enc, W_p1, W_p2, W_po, W_j1, W_j2, wt); // 4
    lens_kernel<<<1, 32>>>(features_len, out_lens);                               // 5
    fused_chain<<<MM / 128, 256, SMEMSZ>>>(                                       // 6 <- profiled
        encbf, wt, b_enc, b_p1, b_p2, b_po, b_j1, b_j2,
        enc, pred, logits, hsum, hb1, hb2);
    logsoftmax3<<<dim3(MM, 3), 256>>>(logits, pred, enc, out);                    // 7
}

// round 7
// speedup vs baseline: 1.2495x; 1.2495x over previous
#include <cuda_runtime.h>
#include <cuda_bf16.h>
#include <math.h>
#include <stdint.h>

#if !defined(__CUDA_ARCH__) || defined(__CUDA_ARCH_FEAT_SM103_ALL) || \
    defined(__CUDA_ARCH_FEAT_SM100_ALL) || defined(__CUDA_ARCH_FEAT_SM101_ALL) || \
    defined(__CUDA_ARCH_FEAT_SM110_ALL)
#define HAS_TC 1
#else
#define HAS_TC 0
#endif

#define BB 16
#define TT 2000
#define MM (BB*TT)
#define DENC 512
#define VV 1024
#define EE 256
#define PP 640
#define JJ 640

#define BM 128
#define BK 64

// ---------------- scratch ----------------
__device__ float g_enc[(size_t)MM * VV];
__device__ float g_pred[(size_t)MM * VV];
__device__ float g_logits[(size_t)MM * VV];
__device__ __nv_bfloat16 g_hsum[(size_t)MM * VV];
__device__ __nv_bfloat16 g_hb1[(size_t)MM * PP];
__device__ __nv_bfloat16 g_hb2[(size_t)MM * PP];
__device__ __nv_bfloat16 g_encbf[(size_t)MM * DENC];
__device__ __nv_bfloat16 g_embbf[(size_t)VV * EE];
__device__ __nv_bfloat16 g_wt[4u * 1024u * 1024u];
__device__ int2  g_ctx[MM];

#define O_ENC 0
#define O_P1  524288
#define O_P2  851968
#define O_PO  1261568
#define O_J1  1916928
#define O_J2  2572288

__device__ __forceinline__ uint32_t smem_u32(const void* p) {
    uint32_t a;
    asm("{ .reg .u64 t; cvta.to.shared.u64 t, %1; cvt.u32.u64 %0, t; }" : "=r"(a) : "l"(p));
    return a;
}
#define SWZ(b) ((b) ^ (((b) >> 3) & 0x70))

#if HAS_TC
__device__ __forceinline__ uint32_t elect1() {
    uint32_t p;
    asm volatile("{\n\t.reg .pred p;\n\telect.sync _|p, 0xFFFFFFFF;\n\tselp.b32 %0, 1, 0, p;\n\t}" : "=r"(p));
    return p;
}
__device__ __forceinline__ uint64_t make_desc(uint32_t addr) {
    return ((uint64_t)((addr >> 4) & 0x3FFF))
         | (1ull << 16) | (64ull << 32) | (1ull << 46) | (2ull << 61);
}
__device__ __forceinline__ void cp16(uint32_t s, const void* g) {
    asm volatile("cp.async.cg.shared.global [%0], [%1], 16;\n" :: "r"(s), "l"(g));
}
#define CP_COMMIT() asm volatile("cp.async.commit_group;\n" ::: "memory")

__device__ __forceinline__ void mbar_init(uint32_t a, uint32_t cnt) {
    asm volatile("mbarrier.init.shared.b64 [%0], %1;" :: "r"(a), "r"(cnt) : "memory");
}
__device__ __forceinline__ void mbar_wait(uint32_t a, uint32_t parity) {
    uint32_t done = 0;
    while (!done) {
        asm volatile("{\n\t.reg .pred p;\n\t"
            "mbarrier.try_wait.parity.acquire.cta.shared::cta.b64 p, [%1], %2, 0x989680;\n\t"
            "selp.b32 %0, 1, 0, p;\n\t}"
            : "=r"(done) : "r"(a), "r"(parity) : "memory");
    }
}
__device__ __forceinline__ void tc_alloc(uint32_t slot, uint32_t ncols) {
    asm volatile("tcgen05.alloc.cta_group::1.sync.aligned.shared::cta.b32 [%0], %1;"
                 :: "r"(slot), "r"(ncols) : "memory");
}
__device__ __forceinline__ void tc_dealloc(uint32_t tmem, uint32_t ncols) {
    asm volatile("tcgen05.dealloc.cta_group::1.sync.aligned.b32 %0, %1;" :: "r"(tmem), "r"(ncols));
}
__device__ __forceinline__ void tc_relinq() {
    asm volatile("tcgen05.relinquish_alloc_permit.cta_group::1.sync.aligned;");
}
__device__ __forceinline__ void tc_commit(uint32_t mbar) {
    asm volatile("tcgen05.commit.cta_group::1.mbarrier::arrive::one.shared::cluster.b64 [%0];"
                 :: "r"(mbar) : "memory");
}
__device__ __forceinline__ void mma_bf16_ss(uint32_t d, uint64_t ad, uint64_t bd,
                                            uint32_t idesc, uint32_t en) {
    asm volatile(
        "{\n\t.reg .pred p;\n\tsetp.ne.u32 p, %4, 0;\n\t"
        "tcgen05.mma.cta_group::1.kind::f16 [%0], %1, %2, %3, p;\n\t}"
        :: "r"(d), "l"(ad), "l"(bd), "r"(idesc), "r"(en) : "memory");
}
__device__ __forceinline__ void ldtm32(uint32_t* r, uint32_t a) {
    asm volatile(
        "tcgen05.ld.sync.aligned.32x32b.x32.b32 "
        "{%0, %1, %2, %3, %4, %5, %6, %7, %8, %9, %10, %11, %12, %13, %14, %15, "
        " %16, %17, %18, %19, %20, %21, %22, %23, %24, %25, %26, %27, %28, %29, %30, %31}, [%32];"
        : "=r"(r[0]), "=r"(r[1]), "=r"(r[2]), "=r"(r[3]), "=r"(r[4]), "=r"(r[5]), "=r"(r[6]), "=r"(r[7]),
          "=r"(r[8]), "=r"(r[9]), "=r"(r[10]), "=r"(r[11]), "=r"(r[12]), "=r"(r[13]), "=r"(r[14]), "=r"(r[15]),
          "=r"(r[16]), "=r"(r[17]), "=r"(r[18]), "=r"(r[19]), "=r"(r[20]), "=r"(r[21]), "=r"(r[22]), "=r"(r[23]),
          "=r"(r[24]), "=r"(r[25]), "=r"(r[26]), "=r"(r[27]), "=r"(r[28]), "=r"(r[29]), "=r"(r[30]), "=r"(r[31])
        : "r"(a));
}
#define TC_WAIT_LD()  asm volatile("tcgen05.wait::ld.sync.aligned;" ::: "memory")
#define TC_FENCE_AFTER()  asm volatile("tcgen05.fence::after_thread_sync;" ::: "memory")
#define TC_FENCE_BEFORE() asm volatile("tcgen05.fence::before_thread_sync;" ::: "memory")
#endif  // HAS_TC

// ---------------- merged weight transpose (fp32 [K,N] -> bf16 [N,K]) ----------------
__global__ void transpose_all(
    const float* __restrict__ W0, const float* __restrict__ W1, const float* __restrict__ W2,
    const float* __restrict__ W3, const float* __restrict__ W4, const float* __restrict__ W5,
    __nv_bfloat16* __restrict__ wt)
{
    __shared__ float tile[32][33];
    const float* W; __nv_bfloat16* Wt; int K, N;
    switch (blockIdx.y) {
        case 0:  W = W0; Wt = wt + O_ENC; K = DENC; N = VV; break;
        case 1:  W = W1; Wt = wt + O_P1;  K = DENC; N = PP; break;
        case 2:  W = W2; Wt = wt + O_P2;  K = PP;   N = PP; break;
        case 3:  W = W3; Wt = wt + O_PO;  K = PP;   N = VV; break;
        case 4:  W = W4; Wt = wt + O_J1;  K = VV;   N = JJ; break;
        default: W = W5; Wt = wt + O_J2;  K = JJ;   N = VV; break;
    }
    int tn = N / 32;
    if ((int)blockIdx.x >= tn * (K / 32)) return;
    int n0 = ((int)blockIdx.x % tn) * 32, k0 = ((int)blockIdx.x / tn) * 32;
    int tx = threadIdx.x, ty = threadIdx.y;
    #pragma unroll
    for (int i = 0; i < 32; i += 8)
        tile[ty + i][tx] = W[(size_t)(k0 + ty + i) * N + n0 + tx];
    __syncthreads();
    #pragma unroll
    for (int i = 0; i < 32; i += 8)
        Wt[(size_t)(n0 + ty + i) * K + k0 + tx] = __float2bfloat16(tile[tx][ty + i]);
}

__global__ void f2bf_kernel(const float* __restrict__ s, __nv_bfloat16* __restrict__ d, int n4) {
    int i = blockIdx.x * blockDim.x + threadIdx.x;
    if (i >= n4) return;
    float4 v = reinterpret_cast<const float4*>(s)[i];
    reinterpret_cast<__nv_bfloat162*>(d)[i * 2]     = __floats2bfloat162_rn(v.x, v.y);
    reinterpret_cast<__nv_bfloat162*>(d)[i * 2 + 1] = __floats2bfloat162_rn(v.z, v.w);
}

__global__ void ctx_kernel(const int* __restrict__ targets) {
    __shared__ int pmax[2048];
    __shared__ int tot[256];
    int b = blockIdx.x;
    const int* tg = targets + (size_t)b * TT;
    int tid = threadIdx.x;
    int loc[8];
    int run = -1;
    #pragma unroll
    for (int j = 0; j < 8; ++j) {
        int t = tid * 8 + j;
        int p = (t < TT && tg[t] != 0) ? t : -1;
        run = max(run, p);
        loc[j] = run;
    }
    tot[tid] = run;
    __syncthreads();
    if (tid == 0) {
        int r = -1;
        for (int i = 0; i < 256; ++i) { int v = tot[i]; tot[i] = r; r = max(r, v); }
    }
    __syncthreads();
    int off = tot[tid];
    #pragma unroll
    for (int j = 0; j < 8; ++j) pmax[tid * 8 + j] = max(off, loc[j]);
    __syncthreads();
    for (int t = tid; t < TT; t += 256) {
        int p1 = (t >= 1) ? pmax[t - 1] : -1;
        int p2 = (t >= 2) ? pmax[t - 2] : -1;
        g_ctx[(size_t)b * TT + t] = make_int2(p1 >= 0 ? tg[p1] : 0, p2 >= 0 ? tg[p2] : 0);
    }
}

// ---------------- tcgen05 bf16 GEMM (occ-2/3 tiles) ----------------
// C = act(A @ Bt^T + bias). Bt [N,K] bf16. 2-stage cp.async pipeline.
// ASRC: 0 = A[M,K] bf16; 1 = gather from g_embbf via g_ctx.
// OUTMODE: 0 = fp32 C; 1 = bf16 C; 2 = fp32 C + bf16 Csum = C + Cadd(fp32).
template<int BN, int ASRC, int ACT, int OUTMODE>
__global__ __launch_bounds__(256) void mma_gemm(
    const __nv_bfloat16* __restrict__ A, const __nv_bfloat16* __restrict__ Bt,
    const float* __restrict__ bias,
    void* __restrict__ Cv, const float* __restrict__ Cadd, __nv_bfloat16* __restrict__ Csum,
    int K, int ldc)
{
#if HAS_TC
    extern __shared__ char smem[];
    const uint32_t sbase = smem_u32(smem);
    const int tid = threadIdx.x;
    const int wid = tid >> 5;
    const int lane = tid & 31;
    const int gRow = blockIdx.x * BM;
    const int ncol0 = blockIdx.y * BN;
    const __nv_bfloat16* BtT = Bt + (size_t)ncol0 * K;

    const uint32_t ctrl = sbase;
    const uint32_t mb   = sbase + 16;
    const uint32_t tile0 = (sbase + 1024 + 1023) & ~1023u;
    const int STAGE = (BM + BN) * BK * 2;

    if (wid == 0) tc_alloc(ctrl, BN);
    if (tid == 0) { mbar_init(mb, 1); mbar_init(mb + 8, 1); }
    __syncthreads();
    uint32_t tmem;
    asm volatile("ld.shared.b32 %0, [%1];" : "=r"(tmem) : "r"(ctrl));

    const int KT = K / BK;

    auto load_stage = [&](int ki, int s) {
        const int k0 = ki * BK;
        const uint32_t ab = tile0 + s * STAGE;
        const uint32_t bb = ab + BM * BK * 2;
        #pragma unroll
        for (int t = 0; t < 4; t++) {
            int q = tid + t * 256, r = q >> 3, cv = q & 7;
            const __nv_bfloat16* gp;
            if (ASRC == 1) {
                int2 cx = g_ctx[gRow + r];
                int idx = (k0 < 256) ? cx.x : cx.y;
                gp = g_embbf + (size_t)idx * EE + ((k0 & 255) + cv * 8);
            } else {
                gp = A + (size_t)(gRow + r) * K + (k0 + cv * 8);
            }
            cp16(ab + SWZ(r * 128 + cv * 16), gp);
        }
        #pragma unroll
        for (int t = 0; t < BN / 32; t++) {
            int q = tid + t * 256, r = q >> 3, cv = q & 7;
            cp16(bb + SWZ(r * 128 + cv * 16), BtT + (size_t)r * K + (k0 + cv * 8));
        }
    };

    load_stage(0, 0); CP_COMMIT();
    load_stage(1, 1); CP_COMMIT();

    const uint32_t idesc = (1u << 4) | (1u << 7) | (1u << 10)
                         | ((uint32_t)(BN / 8) << 17) | ((uint32_t)(BM / 16) << 24);

    for (int i = 0; i < KT; i++) {
        const int s = i & 1;
        asm volatile("cp.async.wait_group 1;\n" ::: "memory");
        __syncthreads();
        if (wid == 0) {
            asm volatile("fence.proxy.async.shared::cta;" ::: "memory");
            TC_FENCE_AFTER();
            if (elect1()) {
                const uint32_t ab = tile0 + s * STAGE;
                const uint32_t bb = ab + BM * BK * 2;
                uint64_t ad = make_desc(ab), bd = make_desc(bb);
                #pragma unroll
                for (int kk = 0; kk < 4; kk++)
                    mma_bf16_ss(tmem, ad + kk * 2, bd + kk * 2, idesc, (i | kk) ? 1u : 0u);
                tc_commit(mb + 8 * s);
            }
        }
        if (i + 2 < KT) {
            mbar_wait(mb + 8 * s, (i / 2) & 1);
            load_stage(i + 2, s);
        }
        CP_COMMIT();
    }
    mbar_wait(mb + 8 * ((KT - 1) & 1), ((KT - 1) / 2) & 1);
    TC_FENCE_AFTER();
    __syncthreads();

    // ---- epilogue ----
    if (wid < 4) {
        const int row = gRow + wid * 32 + lane;
        const float* bs = bias + ncol0;
        float* crowf = (OUTMODE != 1) ? ((float*)Cv + (size_t)row * ldc + ncol0) : nullptr;
        __nv_bfloat16* crowh = (OUTMODE == 1) ? ((__nv_bfloat16*)Cv + (size_t)row * ldc + ncol0) : nullptr;
        const float* erow = (OUTMODE == 2) ? (Cadd + (size_t)row * ldc + ncol0) : nullptr;
        __nv_bfloat16* srow = (OUTMODE == 2) ? (Csum + (size_t)row * ldc + ncol0) : nullptr;
        #pragma unroll
        for (int c0 = 0; c0 < BN; c0 += 32) {
            uint32_t r[32];
            ldtm32(r, tmem + c0);
            TC_WAIT_LD();
            #pragma unroll
            for (int j = 0; j < 32; j += 4) {
                float4 b4 = *reinterpret_cast<const float4*>(bs + c0 + j);
                float4 o;
                o.x = __uint_as_float(r[j + 0]) + b4.x;
                o.y = __uint_as_float(r[j + 1]) + b4.y;
                o.z = __uint_as_float(r[j + 2]) + b4.z;
                o.w = __uint_as_float(r[j + 3]) + b4.w;
                if (ACT) { o.x = tanhf(o.x); o.y = tanhf(o.y); o.z = tanhf(o.z); o.w = tanhf(o.w); }
                if (OUTMODE == 1) {
                    reinterpret_cast<__nv_bfloat162*>(crowh + c0 + j)[0] = __floats2bfloat162_rn(o.x, o.y);
                    reinterpret_cast<__nv_bfloat162*>(crowh + c0 + j)[1] = __floats2bfloat162_rn(o.z, o.w);
                } else {
                    *reinterpret_cast<float4*>(crowf + c0 + j) = o;
                    if (OUTMODE == 2) {
                        float4 e4 = *reinterpret_cast<const float4*>(erow + c0 + j);
                        reinterpret_cast<__nv_bfloat162*>(srow + c0 + j)[0] = __floats2bfloat162_rn(o.x + e4.x, o.y + e4.y);
                        reinterpret_cast<__nv_bfloat162*>(srow + c0 + j)[1] = __floats2bfloat162_rn(o.z + e4.z, o.w + e4.w);
                    }
                }
            }
        }
        TC_FENCE_BEFORE();
    }
    __syncthreads();
    if (wid == 0) {
        tc_relinq();
        tc_dealloc(tmem, BN);
    }
#else
    // ======== FFMA fallback (compute_103 PTX pass; never selected at runtime) ========
    __shared__ float As[8][128];
    __shared__ float Bs[8][128];
    const int tid = threadIdx.x;
    const int tx = tid & 15, ty = tid >> 4;
    const int gRow = blockIdx.x * BM;
    const int ncol0 = blockIdx.y * BN;
    const __nv_bfloat16* BtT = Bt + (size_t)ncol0 * K;

    for (int nc = 0; nc < BN; nc += 128) {
        float acc[8][8];
        #pragma unroll
        for (int i = 0; i < 8; ++i)
            #pragma unroll
            for (int j = 0; j < 8; ++j) acc[i][j] = 0.f;

        for (int k0 = 0; k0 < K; k0 += 8) {
            int rowA = tid >> 1, colA = (tid & 1) * 4;
            int m = gRow + rowA;
            const __nv_bfloat16* ap;
            if (ASRC == 1) {
                int2 cx = g_ctx[m];
                int k = k0 + colA;
                int idx = (k < 256) ? cx.x : cx.y;
                ap = g_embbf + (size_t)idx * EE + (k & 255);
            } else {
                ap = A + (size_t)m * K + k0 + colA;
            }
            #pragma unroll
            for (int u = 0; u < 4; u++) As[colA + u][rowA] = __bfloat162float(ap[u]);

            int nB = tid >> 1, kB = (tid & 1) * 4;
            const __nv_bfloat16* bp = BtT + (size_t)(nc + nB) * K + k0 + kB;
            #pragma unroll
            for (int u = 0; u < 4; u++) Bs[kB + u][nB] = __bfloat162float(bp[u]);
            __syncthreads();

            #pragma unroll
            for (int kk = 0; kk < 8; ++kk) {
                float ar[8], br[8];
                #pragma unroll
                for (int i = 0; i < 8; ++i) ar[i] = As[kk][ty * 8 + i];
                #pragma unroll
                for (int j = 0; j < 8; ++j) br[j] = Bs[kk][tx * 8 + j];
                #pragma unroll
                for (int i = 0; i < 8; ++i)
                    #pragma unroll
                    for (int j = 0; j < 8; ++j)
                        acc[i][j] = fmaf(ar[i], br[j], acc[i][j]);
            }
            __syncthreads();
        }

        #pragma unroll
        for (int i = 0; i < 8; ++i) {
            int row = gRow + ty * 8 + i;
            int col = ncol0 + nc + tx * 8;
            #pragma unroll
            for (int j = 0; j < 8; ++j) {
                float o = acc[i][j] + bias[col + j];
                if (ACT) o = tanhf(o);
                if (OUTMODE == 1) {
                    ((__nv_bfloat16*)Cv)[(size_t)row * ldc + col + j] = __float2bfloat16(o);
                } else {
                    ((float*)Cv)[(size_t)row * ldc + col + j] = o;
                    if (OUTMODE == 2)
                        Csum[(size_t)row * ldc + col + j] =
                            __float2bfloat16(o + Cadd[(size_t)row * ldc + col + j]);
                }
            }
        }
    }
#endif
}

// ---------------- merged log-softmax (3 tensors) ----------------
__global__ __launch_bounds__(256) void logsoftmax3(
    const float* __restrict__ lg, const float* __restrict__ pd,
    const float* __restrict__ en, float* __restrict__ out)
{
    __shared__ float redm[8];
    __shared__ float reds[8];
    int row = blockIdx.x;
    const float* X; float* Y;
    if (blockIdx.y == 0)      { X = lg; Y = out; }
    else if (blockIdx.y == 1) { X = pd; Y = out + (size_t)MM * VV; }
    else                      { X = en; Y = out + 2 * (size_t)MM * VV; }
    int tid = threadIdx.x;
    float4 x = reinterpret_cast<const float4*>(X + (size_t)row * VV)[tid];
    float m = fmaxf(fmaxf(x.x, x.y), fmaxf(x.z, x.w));
    #pragma unroll
    for (int o = 16; o; o >>= 1) m = fmaxf(m, __shfl_xor_sync(0xffffffffu, m, o));
    if ((tid & 31) == 0) redm[tid >> 5] = m;
    __syncthreads();
    float mx = redm[0];
    #pragma unroll
    for (int i = 1; i < 8; ++i) mx = fmaxf(mx, redm[i]);
    float s = expf(x.x - mx) + expf(x.y - mx) + expf(x.z - mx) + expf(x.w - mx);
    #pragma unroll
    for (int o = 16; o; o >>= 1) s += __shfl_xor_sync(0xffffffffu, s, o);
    if ((tid & 31) == 0) reds[tid >> 5] = s;
    __syncthreads();
    float sum = 0.f;
    #pragma unroll
    for (int i = 0; i < 8; ++i) sum += reds[i];
    float lse = mx + logf(sum);
    float4 y = make_float4(x.x - lse, x.y - lse, x.z - lse, x.w - lse);
    reinterpret_cast<float4*>(Y + (size_t)row * VV)[tid] = y;
}

__global__ void lens_kernel(const int* __restrict__ flen, float* __restrict__ out) {
    int i = threadIdx.x;
    if (i < BB) out[i] = (float)flen[i];
}

// ---------------- launch ----------------
extern "C" void kernel_launch(void* const* d_in, const int* in_sizes, int n_in,
                              void* d_out, int out_size)
{
    const float* encoder_out  = (const float*)d_in[0];
    const int*   features_len = (const int*)  d_in[1];
    const int*   targets      = (const int*)  d_in[2];
    const float* W_enc = (const float*)d_in[3];
    const float* b_enc = (const float*)d_in[4];
    const float* emb   = (const float*)d_in[5];
    const float* W_p1  = (const float*)d_in[6];
    const float* b_p1  = (const float*)d_in[7];
    const float* W_p2  = (const float*)d_in[8];
    const float* b_p2  = (const float*)d_in[9];
    const float* W_po  = (const float*)d_in[10];
    const float* b_po  = (const float*)d_in[11];
    const float* W_j1  = (const float*)d_in[12];
    const float* b_j1  = (const float*)d_in[13];
    const float* W_j2  = (const float*)d_in[14];
    const float* b_j2  = (const float*)d_in[15];

    float *enc, *pred, *logits;
    __nv_bfloat16 *hsum, *hb1, *hb2, *encbf, *embbf, *wt;
    cudaGetSymbolAddress((void**)&enc,    g_enc);
    cudaGetSymbolAddress((void**)&pred,   g_pred);
    cudaGetSymbolAddress((void**)&logits, g_logits);
    cudaGetSymbolAddress((void**)&hsum,   g_hsum);
    cudaGetSymbolAddress((void**)&hb1,    g_hb1);
    cudaGetSymbolAddress((void**)&hb2,    g_hb2);
    cudaGetSymbolAddress((void**)&encbf,  g_encbf);
    cudaGetSymbolAddress((void**)&embbf,  g_embbf);
    cudaGetSymbolAddress((void**)&wt,     g_wt);

    float* out = (float*)d_out;
    float* out_lens = out + 3 * (size_t)MM * VV;

    const int S256 = 2048 + 2 * (BM + 256) * BK * 2;   // 100352 -> occ 2
    const int S128 = 2048 + 2 * (BM + 128) * BK * 2;   // 67584  -> occ 3
    cudaFuncSetAttribute(mma_gemm<256,0,0,0>, cudaFuncAttributeMaxDynamicSharedMemorySize, S256);
    cudaFuncSetAttribute(mma_gemm<256,1,1,1>, cudaFuncAttributeMaxDynamicSharedMemorySize, S256);
    cudaFuncSetAttribute(mma_gemm<256,0,1,1>, cudaFuncAttributeMaxDynamicSharedMemorySize, S256);
    cudaFuncSetAttribute(mma_gemm<256,0,0,2>, cudaFuncAttributeMaxDynamicSharedMemorySize, S256);
    cudaFuncSetAttribute(mma_gemm<128,1,1,1>, cudaFuncAttributeMaxDynamicSharedMemorySize, S128);
    cudaFuncSetAttribute(mma_gemm<128,0,1,1>, cudaFuncAttributeMaxDynamicSharedMemorySize, S128);

    const int MT = MM / BM;  // 250

    // prep launches (1-5)
    ctx_kernel<<<BB, 256>>>(targets);
    f2bf_kernel<<<(MM * DENC / 4 + 255) / 256, 256>>>(encoder_out, encbf, MM * DENC / 4);
    f2bf_kernel<<<(VV * EE / 4 + 255) / 256, 256>>>(emb, embbf, VV * EE / 4);
    transpose_all<<<dim3(640, 6), dim3(32, 8)>>>(W_enc, W_p1, W_p2, W_po, W_j1, W_j2, wt);
    lens_kernel<<<1, 32>>>(features_len, out_lens);

    // 2. enc = encoder_out @ W_enc + b_enc  (fp32 out)      [launch 6 - profiled]
    mma_gemm<256,0,0,0><<<dim3(MT, 4), 256, S256>>>(
        encbf, wt + O_ENC, b_enc, enc, nullptr, nullptr, DENC, VV);

    // 3. a1 = tanh(gather @ W_p1 + b_p1)  (bf16 out)
    mma_gemm<256,1,1,1><<<dim3(MT, 2), 256, S256>>>(
        nullptr, wt + O_P1, b_p1, hb1, nullptr, nullptr, DENC, PP);
    mma_gemm<128,1,1,1><<<dim3(MT, 1), 256, S128>>>(
        nullptr, wt + O_P1 + (size_t)512 * DENC, b_p1 + 512, hb1 + 512, nullptr, nullptr, DENC, PP);

    // 4. a2 = tanh(a1 @ W_p2 + b_p2)  (bf16 out)
    mma_gemm<256,0,1,1><<<dim3(MT, 2), 256, S256>>>(
        hb1, wt + O_P2, b_p2, hb2, nullptr, nullptr, PP, PP);
    mma_gemm<128,0,1,1><<<dim3(MT, 1), 256, S128>>>(
        hb1, wt + O_P2 + (size_t)512 * PP, b_p2 + 512, hb2 + 512, nullptr, nullptr, PP, PP);

    // 5. pred = a2 @ W_po + b_po (fp32) ; hsum = bf16(pred + enc)
    mma_gemm<256,0,0,2><<<dim3(MT, 4), 256, S256>>>(
        hb2, wt + O_PO, b_po, pred, enc, hsum, PP, VV);

    // 6. h = tanh(hsum @ W_j1 + b_j1)  (bf16 out)
    mma_gemm<256,0,1,1><<<dim3(MT, 2), 256, S256>>>(
        hsum, wt + O_J1, b_j1, hb1, nullptr, nullptr, VV, JJ);
    mma_gemm<128,0,1,1><<<dim3(MT, 1), 256, S128>>>(
        hsum, wt + O_J1 + (size_t)512 * VV, b_j1 + 512, hb1 + 512, nullptr, nullptr, VV, JJ);

    // 7. logits = h @ W_j2 + b_j2  (fp32 out)
    mma_gemm<256,0,0,0><<<dim3(MT, 4), 256, S256>>>(
        hb1, wt + O_J2, b_j2, logits, nullptr, nullptr, JJ, VV);

    // 8. log-softmaxes (merged)
    logsoftmax3<<<dim3(MM, 3), 256>>>(logits, pred, enc, out);
}

// round 8
// speedup vs baseline: 1.3598x; 1.0883x over previous
#include <cuda_runtime.h>
#include <cuda_bf16.h>
#include <math.h>
#include <stdint.h>

#if !defined(__CUDA_ARCH__) || defined(__CUDA_ARCH_FEAT_SM103_ALL) || \
    defined(__CUDA_ARCH_FEAT_SM100_ALL) || defined(__CUDA_ARCH_FEAT_SM101_ALL) || \
    defined(__CUDA_ARCH_FEAT_SM110_ALL)
#define HAS_TC 1
#else
#define HAS_TC 0
#endif

#define BB 16
#define TT 2000
#define MM (BB*TT)
#define DENC 512
#define VV 1024
#define EE 256
#define PP 640
#define JJ 640

#define BM 128
#define BK 64
#define NS 3

// ---------------- scratch ----------------
__device__ float g_enc[(size_t)MM * VV];
__device__ float g_pred[(size_t)MM * VV];
__device__ float g_logits[(size_t)MM * VV];
__device__ __nv_bfloat16 g_hsum[(size_t)MM * VV];
__device__ __nv_bfloat16 g_hb1[(size_t)MM * PP];
__device__ __nv_bfloat16 g_hb2[(size_t)MM * PP];
__device__ __nv_bfloat16 g_encbf[(size_t)MM * DENC];
__device__ __nv_bfloat16 g_embbf[(size_t)VV * EE];
__device__ __nv_bfloat16 g_wt[4u * 1024u * 1024u];
__device__ int2  g_ctx[MM];

#define O_ENC 0
#define O_P1  524288
#define O_P2  851968
#define O_PO  1261568
#define O_J1  1916928
#define O_J2  2572288

__device__ __forceinline__ uint32_t smem_u32(const void* p) {
    uint32_t a;
    asm("{ .reg .u64 t; cvta.to.shared.u64 t, %1; cvt.u32.u64 %0, t; }" : "=r"(a) : "l"(p));
    return a;
}
#define SWZ(b) ((b) ^ (((b) >> 3) & 0x70))

#if HAS_TC
__device__ __forceinline__ uint32_t elect1() {
    uint32_t p;
    asm volatile("{\n\t.reg .pred p;\n\telect.sync _|p, 0xFFFFFFFF;\n\tselp.b32 %0, 1, 0, p;\n\t}" : "=r"(p));
    return p;
}
__device__ __forceinline__ uint64_t make_desc(uint32_t addr) {
    return ((uint64_t)((addr >> 4) & 0x3FFF))
         | (1ull << 16) | (64ull << 32) | (1ull << 46) | (2ull << 61);
}
__device__ __forceinline__ void cp16(uint32_t s, const void* g) {
    asm volatile("cp.async.cg.shared.global [%0], [%1], 16;\n" :: "r"(s), "l"(g));
}
#define CP_COMMIT() asm volatile("cp.async.commit_group;\n" ::: "memory")

__device__ __forceinline__ void mbar_init(uint32_t a, uint32_t cnt) {
    asm volatile("mbarrier.init.shared.b64 [%0], %1;" :: "r"(a), "r"(cnt) : "memory");
}
__device__ __forceinline__ void mbar_wait(uint32_t a, uint32_t parity) {
    uint32_t done = 0;
    while (!done) {
        asm volatile("{\n\t.reg .pred p;\n\t"
            "mbarrier.try_wait.parity.acquire.cta.shared::cta.b64 p, [%1], %2, 0x989680;\n\t"
            "selp.b32 %0, 1, 0, p;\n\t}"
            : "=r"(done) : "r"(a), "r"(parity) : "memory");
    }
}
__device__ __forceinline__ void tc_alloc(uint32_t slot, uint32_t ncols) {
    asm volatile("tcgen05.alloc.cta_group::1.sync.aligned.shared::cta.b32 [%0], %1;"
                 :: "r"(slot), "r"(ncols) : "memory");
}
__device__ __forceinline__ void tc_dealloc(uint32_t tmem, uint32_t ncols) {
    asm volatile("tcgen05.dealloc.cta_group::1.sync.aligned.b32 %0, %1;" :: "r"(tmem), "r"(ncols));
}
__device__ __forceinline__ void tc_relinq() {
    asm volatile("tcgen05.relinquish_alloc_permit.cta_group::1.sync.aligned;");
}
__device__ __forceinline__ void tc_commit(uint32_t mbar) {
    asm volatile("tcgen05.commit.cta_group::1.mbarrier::arrive::one.shared::cluster.b64 [%0];"
                 :: "r"(mbar) : "memory");
}
__device__ __forceinline__ void mma_bf16_ss(uint32_t d, uint64_t ad, uint64_t bd,
                                            uint32_t idesc, uint32_t en) {
    asm volatile(
        "{\n\t.reg .pred p;\n\tsetp.ne.u32 p, %4, 0;\n\t"
        "tcgen05.mma.cta_group::1.kind::f16 [%0], %1, %2, %3, p;\n\t}"
        :: "r"(d), "l"(ad), "l"(bd), "r"(idesc), "r"(en) : "memory");
}
__device__ __forceinline__ void ldtm32(uint32_t* r, uint32_t a) {
    asm volatile(
        "tcgen05.ld.sync.aligned.32x32b.x32.b32 "
        "{%0, %1, %2, %3, %4, %5, %6, %7, %8, %9, %10, %11, %12, %13, %14, %15, "
        " %16, %17, %18, %19, %20, %21, %22, %23, %24, %25, %26, %27, %28, %29, %30, %31}, [%32];"
        : "=r"(r[0]), "=r"(r[1]), "=r"(r[2]), "=r"(r[3]), "=r"(r[4]), "=r"(r[5]), "=r"(r[6]), "=r"(r[7]),
          "=r"(r[8]), "=r"(r[9]), "=r"(r[10]), "=r"(r[11]), "=r"(r[12]), "=r"(r[13]), "=r"(r[14]), "=r"(r[15]),
          "=r"(r[16]), "=r"(r[17]), "=r"(r[18]), "=r"(r[19]), "=r"(r[20]), "=r"(r[21]), "=r"(r[22]), "=r"(r[23]),
          "=r"(r[24]), "=r"(r[25]), "=r"(r[26]), "=r"(r[27]), "=r"(r[28]), "=r"(r[29]), "=r"(r[30]), "=r"(r[31])
        : "r"(a));
}
#define TC_WAIT_LD()  asm volatile("tcgen05.wait::ld.sync.aligned;" ::: "memory")
#define TC_FENCE_AFTER()  asm volatile("tcgen05.fence::after_thread_sync;" ::: "memory")
#define TC_FENCE_BEFORE() asm volatile("tcgen05.fence::before_thread_sync;" ::: "memory")
#endif  // HAS_TC

// ---------------- fused prep: ctx + lens + f2bf(emb) + transpose + f2bf(enc) ----------------
__global__ __launch_bounds__(256) void prep_kernel(
    const int* __restrict__ targets, const float* __restrict__ encoder_out,
    const float* __restrict__ emb,
    const float* __restrict__ W0, const float* __restrict__ W1, const float* __restrict__ W2,
    const float* __restrict__ W3, const float* __restrict__ W4, const float* __restrict__ W5,
    __nv_bfloat16* __restrict__ wt, __nv_bfloat16* __restrict__ encbf,
    __nv_bfloat16* __restrict__ embbf,
    const int* __restrict__ flen, float* __restrict__ out_lens)
{
    __shared__ int pmax[2048];
    __shared__ int tot[256];
    __shared__ float tile[32][33];
    const int blk = blockIdx.x;
    const int tid = threadIdx.x;

    if (blk < 16) {
        // viterbi context scan for batch blk
        const int* tg = targets + (size_t)blk * TT;
        int loc[8];
        int run = -1;
        #pragma unroll
        for (int j = 0; j < 8; ++j) {
            int t = tid * 8 + j;
            int p = (t < TT && tg[t] != 0) ? t : -1;
            run = max(run, p);
            loc[j] = run;
        }
        tot[tid] = run;
        __syncthreads();
        if (tid == 0) {
            int r = -1;
            for (int i = 0; i < 256; ++i) { int v = tot[i]; tot[i] = r; r = max(r, v); }
        }
        __syncthreads();
        int off = tot[tid];
        #pragma unroll
        for (int j = 0; j < 8; ++j) pmax[tid * 8 + j] = max(off, loc[j]);
        __syncthreads();
        for (int t = tid; t < TT; t += 256) {
            int p1 = (t >= 1) ? pmax[t - 1] : -1;
            int p2 = (t >= 2) ? pmax[t - 2] : -1;
            g_ctx[(size_t)blk * TT + t] = make_int2(p1 >= 0 ? tg[p1] : 0, p2 >= 0 ? tg[p2] : 0);
        }
    } else if (blk == 16) {
        if (tid < BB) out_lens[tid] = (float)flen[tid];
    } else if (blk < 273) {
        // f2bf emb: 65536 float4 elements
        int i = (blk - 17) * 256 + tid;
        float4 v = reinterpret_cast<const float4*>(emb)[i];
        reinterpret_cast<__nv_bfloat162*>(embbf)[i * 2]     = __floats2bfloat162_rn(v.x, v.y);
        reinterpret_cast<__nv_bfloat162*>(embbf)[i * 2 + 1] = __floats2bfloat162_rn(v.z, v.w);
    } else if (blk < 4113) {
        // weight transpose: t in [0,3840), 640 tiles per weight
        int t = blk - 273;
        int wsel = t / 640, tidx = t % 640;
        const float* W; __nv_bfloat16* Wt; int K, N;
        switch (wsel) {
            case 0:  W = W0; Wt = wt + O_ENC; K = DENC; N = VV; break;
            case 1:  W = W1; Wt = wt + O_P1;  K = DENC; N = PP; break;
            case 2:  W = W2; Wt = wt + O_P2;  K = PP;   N = PP; break;
            case 3:  W = W3; Wt = wt + O_PO;  K = PP;   N = VV; break;
            case 4:  W = W4; Wt = wt + O_J1;  K = VV;   N = JJ; break;
            default: W = W5; Wt = wt + O_J2;  K = JJ;   N = VV; break;
        }
        int tn = N / 32;
        if (tidx < tn * (K / 32)) {
            int n0 = (tidx % tn) * 32, k0 = (tidx / tn) * 32;
            int tx = tid & 31, ty = tid >> 5;
            #pragma unroll
            for (int i = 0; i < 32; i += 8)
                tile[ty + i][tx] = W[(size_t)(k0 + ty + i) * N + n0 + tx];
            __syncthreads();
            #pragma unroll
            for (int i = 0; i < 32; i += 8)
                Wt[(size_t)(n0 + ty + i) * K + k0 + tx] = __float2bfloat16(tile[tx][ty + i]);
        }
    } else {
        // f2bf encoder_out: 4,096,000 float4 elements
        int i = (blk - 4113) * 256 + tid;
        float4 v = reinterpret_cast<const float4*>(encoder_out)[i];
        reinterpret_cast<__nv_bfloat162*>(encbf)[i * 2]     = __floats2bfloat162_rn(v.x, v.y);
        reinterpret_cast<__nv_bfloat162*>(encbf)[i * 2 + 1] = __floats2bfloat162_rn(v.z, v.w);
    }
}

// ---------------- tcgen05 bf16 GEMM, 3-stage pipeline with true load/MMA overlap ----------------
// C = act(A @ Bt^T + bias). Bt [N,K] bf16 (pre-transposed).
// ASRC: 0 = A[M,K] bf16; 1 = gather from g_embbf via g_ctx.
// OUTMODE: 0 = fp32 C; 1 = bf16 C; 2 = fp32 C + bf16 Csum = C + Cadd(fp32).
template<int BN, int ASRC, int ACT, int OUTMODE>
__global__ __launch_bounds__(256) void mma_gemm(
    const __nv_bfloat16* __restrict__ A, const __nv_bfloat16* __restrict__ Bt,
    const float* __restrict__ bias,
    void* __restrict__ Cv, const float* __restrict__ Cadd, __nv_bfloat16* __restrict__ Csum,
    int K, int ldc)
{
#if HAS_TC
    extern __shared__ char smem[];
    const uint32_t sbase = smem_u32(smem);
    const int tid = threadIdx.x;
    const int wid = tid >> 5;
    const int lane = tid & 31;
    const int gRow = blockIdx.x * BM;
    const int ncol0 = blockIdx.y * BN;
    const __nv_bfloat16* BtT = Bt + (size_t)ncol0 * K;

    const uint32_t ctrl = sbase;
    const uint32_t mb   = sbase + 16;             // NS mbarriers
    const uint32_t tile0 = (sbase + 1024 + 1023) & ~1023u;
    const int STAGE = (BM + BN) * BK * 2;

    if (wid == 0) tc_alloc(ctrl, BN);
    if (tid == 0) { for (int s = 0; s < NS; s++) mbar_init(mb + 8 * s, 1); }
    __syncthreads();
    uint32_t tmem;
    asm volatile("ld.shared.b32 %0, [%1];" : "=r"(tmem) : "r"(ctrl));

    const int KT = K / BK;

    auto load_stage = [&](int ki, int s) {
        const int k0 = ki * BK;
        const uint32_t ab = tile0 + s * STAGE;
        const uint32_t bb = ab + BM * BK * 2;
        #pragma unroll
        for (int t = 0; t < 4; t++) {
            int q = tid + t * 256, r = q >> 3, cv = q & 7;
            const __nv_bfloat16* gp;
            if (ASRC == 1) {
                int2 cx = g_ctx[gRow + r];
                int idx = (k0 < 256) ? cx.x : cx.y;
                gp = g_embbf + (size_t)idx * EE + ((k0 & 255) + cv * 8);
            } else {
                gp = A + (size_t)(gRow + r) * K + (k0 + cv * 8);
            }
            cp16(ab + SWZ(r * 128 + cv * 16), gp);
        }
        #pragma unroll
        for (int t = 0; t < BN / 32; t++) {
            int q = tid + t * 256, r = q >> 3, cv = q & 7;
            cp16(bb + SWZ(r * 128 + cv * 16), BtT + (size_t)r * K + (k0 + cv * 8));
        }
    };

    // prologue: loads lead MMAs by 2 stages
    load_stage(0, 0); CP_COMMIT();
    load_stage(1, 1); CP_COMMIT();

    const uint32_t idesc = (1u << 4) | (1u << 7) | (1u << 10)
                         | ((uint32_t)(BN / 8) << 17) | ((uint32_t)(BM / 16) << 24);

    for (int i = 0; i < KT; i++) {
        const int s = i % NS;
        asm volatile("cp.async.wait_group 1;\n" ::: "memory");   // load(i) complete
        __syncthreads();
        if (wid == 0) {
            asm volatile("fence.proxy.async.shared::cta;" ::: "memory");
            TC_FENCE_AFTER();
            if (elect1()) {
                const uint32_t ab = tile0 + s * STAGE;
                const uint32_t bb = ab + BM * BK * 2;
                uint64_t ad = make_desc(ab), bd = make_desc(bb);
                #pragma unroll
                for (int kk = 0; kk < 4; kk++)
                    mma_bf16_ss(tmem, ad + kk * 2, bd + kk * 2, idesc, (i | kk) ? 1u : 0u);
                tc_commit(mb + 8 * s);
            }
        }
        if (i + 2 < KT) {
            // buffer (i+2)%NS was used by MMA(i-1) — issued a full iteration ago
            if (i >= 1) mbar_wait(mb + 8 * ((i - 1) % NS), ((i - 1) / NS) & 1);
            load_stage(i + 2, (i + 2) % NS);
        }
        CP_COMMIT();
    }
    mbar_wait(mb + 8 * ((KT - 1) % NS), ((KT - 1) / NS) & 1);
    TC_FENCE_AFTER();
    __syncthreads();

    // ---- epilogue ----
    if (wid < 4) {
        const int row = gRow + wid * 32 + lane;
        const float* bs = bias + ncol0;
        float* crowf = (OUTMODE != 1) ? ((float*)Cv + (size_t)row * ldc + ncol0) : nullptr;
        __nv_bfloat16* crowh = (OUTMODE == 1) ? ((__nv_bfloat16*)Cv + (size_t)row * ldc + ncol0) : nullptr;
        const float* erow = (OUTMODE == 2) ? (Cadd + (size_t)row * ldc + ncol0) : nullptr;
        __nv_bfloat16* srow = (OUTMODE == 2) ? (Csum + (size_t)row * ldc + ncol0) : nullptr;
        #pragma unroll
        for (int c0 = 0; c0 < BN; c0 += 32) {
            uint32_t r[32];
            ldtm32(r, tmem + c0);
            TC_WAIT_LD();
            #pragma unroll
            for (int j = 0; j < 32; j += 4) {
                float4 b4 = *reinterpret_cast<const float4*>(bs + c0 + j);
                float4 o;
                o.x = __uint_as_float(r[j + 0]) + b4.x;
                o.y = __uint_as_float(r[j + 1]) + b4.y;
                o.z = __uint_as_float(r[j + 2]) + b4.z;
                o.w = __uint_as_float(r[j + 3]) + b4.w;
                if (ACT) { o.x = tanhf(o.x); o.y = tanhf(o.y); o.z = tanhf(o.z); o.w = tanhf(o.w); }
                if (OUTMODE == 1) {
                    reinterpret_cast<__nv_bfloat162*>(crowh + c0 + j)[0] = __floats2bfloat162_rn(o.x, o.y);
                    reinterpret_cast<__nv_bfloat162*>(crowh + c0 + j)[1] = __floats2bfloat162_rn(o.z, o.w);
                } else {
                    *reinterpret_cast<float4*>(crowf + c0 + j) = o;
                    if (OUTMODE == 2) {
                        float4 e4 = *reinterpret_cast<const float4*>(erow + c0 + j);
                        reinterpret_cast<__nv_bfloat162*>(srow + c0 + j)[0] = __floats2bfloat162_rn(o.x + e4.x, o.y + e4.y);
                        reinterpret_cast<__nv_bfloat162*>(srow + c0 + j)[1] = __floats2bfloat162_rn(o.z + e4.z, o.w + e4.w);
                    }
                }
            }
        }
        TC_FENCE_BEFORE();
    }
    __syncthreads();
    if (wid == 0) {
        tc_relinq();
        tc_dealloc(tmem, BN);
    }
#else
    // ======== FFMA fallback (compute_103 PTX pass; never selected at runtime) ========
    __shared__ float As[8][128];
    __shared__ float Bs[8][128];
    const int tid = threadIdx.x;
    const int tx = tid & 15, ty = tid >> 4;
    const int gRow = blockIdx.x * BM;
    const int ncol0 = blockIdx.y * BN;
    const __nv_bfloat16* BtT = Bt + (size_t)ncol0 * K;

    for (int nc = 0; nc < BN; nc += 128) {
        float acc[8][8];
        #pragma unroll
        for (int i = 0; i < 8; ++i)
            #pragma unroll
            for (int j = 0; j < 8; ++j) acc[i][j] = 0.f;

        for (int k0 = 0; k0 < K; k0 += 8) {
            int rowA = tid >> 1, colA = (tid & 1) * 4;
            int m = gRow + rowA;
            const __nv_bfloat16* ap;
            if (ASRC == 1) {
                int2 cx = g_ctx[m];
                int k = k0 + colA;
                int idx = (k < 256) ? cx.x : cx.y;
                ap = g_embbf + (size_t)idx * EE + (k & 255);
            } else {
                ap = A + (size_t)m * K + k0 + colA;
            }
            #pragma unroll
            for (int u = 0; u < 4; u++) As[colA + u][rowA] = __bfloat162float(ap[u]);

            int nB = tid >> 1, kB = (tid & 1) * 4;
            const __nv_bfloat16* bp = BtT + (size_t)(nc + nB) * K + k0 + kB;
            #pragma unroll
            for (int u = 0; u < 4; u++) Bs[kB + u][nB] = __bfloat162float(bp[u]);
            __syncthreads();

            #pragma unroll
            for (int kk = 0; kk < 8; ++kk) {
                float ar[8], br[8];
                #pragma unroll
                for (int i = 0; i < 8; ++i) ar[i] = As[kk][ty * 8 + i];
                #pragma unroll
                for (int j = 0; j < 8; ++j) br[j] = Bs[kk][tx * 8 + j];
                #pragma unroll
                for (int i = 0; i < 8; ++i)
                    #pragma unroll
                    for (int j = 0; j < 8; ++j)
                        acc[i][j] = fmaf(ar[i], br[j], acc[i][j]);
            }
            __syncthreads();
        }

        #pragma unroll
        for (int i = 0; i < 8; ++i) {
            int row = gRow + ty * 8 + i;
            int col = ncol0 + nc + tx * 8;
            #pragma unroll
            for (int j = 0; j < 8; ++j) {
                float o = acc[i][j] + bias[col + j];
                if (ACT) o = tanhf(o);
                if (OUTMODE == 1) {
                    ((__nv_bfloat16*)Cv)[(size_t)row * ldc + col + j] = __float2bfloat16(o);
                } else {
                    ((float*)Cv)[(size_t)row * ldc + col + j] = o;
                    if (OUTMODE == 2)
                        Csum[(size_t)row * ldc + col + j] =
                            __float2bfloat16(o + Cadd[(size_t)row * ldc + col + j]);
                }
            }
        }
    }
#endif
}

// ---------------- merged log-softmax (3 tensors) ----------------
__global__ __launch_bounds__(256) void logsoftmax3(
    const float* __restrict__ lg, const float* __restrict__ pd,
    const float* __restrict__ en, float* __restrict__ out)
{
    __shared__ float redm[8];
    __shared__ float reds[8];
    int row = blockIdx.x;
    const float* X; float* Y;
    if (blockIdx.y == 0)      { X = lg; Y = out; }
    else if (blockIdx.y == 1) { X = pd; Y = out + (size_t)MM * VV; }
    else                      { X = en; Y = out + 2 * (size_t)MM * VV; }
    int tid = threadIdx.x;
    float4 x = reinterpret_cast<const float4*>(X + (size_t)row * VV)[tid];
    float m = fmaxf(fmaxf(x.x, x.y), fmaxf(x.z, x.w));
    #pragma unroll
    for (int o = 16; o; o >>= 1) m = fmaxf(m, __shfl_xor_sync(0xffffffffu, m, o));
    if ((tid & 31) == 0) redm[tid >> 5] = m;
    __syncthreads();
    float mx = redm[0];
    #pragma unroll
    for (int i = 1; i < 8; ++i) mx = fmaxf(mx, redm[i]);
    float s = expf(x.x - mx) + expf(x.y - mx) + expf(x.z - mx) + expf(x.w - mx);
    #pragma unroll
    for (int o = 16; o; o >>= 1) s += __shfl_xor_sync(0xffffffffu, s, o);
    if ((tid & 31) == 0) reds[tid >> 5] = s;
    __syncthreads();
    float sum = 0.f;
    #pragma unroll
    for (int i = 0; i < 8; ++i) sum += reds[i];
    float lse = mx + logf(sum);
    float4 y = make_float4(x.x - lse, x.y - lse, x.z - lse, x.w - lse);
    reinterpret_cast<float4*>(Y + (size_t)row * VV)[tid] = y;
}

// ---------------- launch ----------------
extern "C" void kernel_launch(void* const* d_in, const int* in_sizes, int n_in,
                              void* d_out, int out_size)
{
    const float* encoder_out  = (const float*)d_in[0];
    const int*   features_len = (const int*)  d_in[1];
    const int*   targets      = (const int*)  d_in[2];
    const float* W_enc = (const float*)d_in[3];
    const float* b_enc = (const float*)d_in[4];
    const float* emb   = (const float*)d_in[5];
    const float* W_p1  = (const float*)d_in[6];
    const float* b_p1  = (const float*)d_in[7];
    const float* W_p2  = (const float*)d_in[8];
    const float* b_p2  = (const float*)d_in[9];
    const float* W_po  = (const float*)d_in[10];
    const float* b_po  = (const float*)d_in[11];
    const float* W_j1  = (const float*)d_in[12];
    const float* b_j1  = (const float*)d_in[13];
    const float* W_j2  = (const float*)d_in[14];
    const float* b_j2  = (const float*)d_in[15];

    float *enc, *pred, *logits;
    __nv_bfloat16 *hsum, *hb1, *hb2, *encbf, *embbf, *wt;
    cudaGetSymbolAddress((void**)&enc,    g_enc);
    cudaGetSymbolAddress((void**)&pred,   g_pred);
    cudaGetSymbolAddress((void**)&logits, g_logits);
    cudaGetSymbolAddress((void**)&hsum,   g_hsum);
    cudaGetSymbolAddress((void**)&hb1,    g_hb1);
    cudaGetSymbolAddress((void**)&hb2,    g_hb2);
    cudaGetSymbolAddress((void**)&encbf,  g_encbf);
    cudaGetSymbolAddress((void**)&embbf,  g_embbf);
    cudaGetSymbolAddress((void**)&wt,     g_wt);

    float* out = (float*)d_out;
    float* out_lens = out + 3 * (size_t)MM * VV;

    const int S256 = 2048 + NS * (BM + 256) * BK * 2;   // 149504 -> occ 1
    const int S128 = 2048 + NS * (BM + 128) * BK * 2;   // 100352 -> occ 2
    cudaFuncSetAttribute(mma_gemm<256,0,0,0>, cudaFuncAttributeMaxDynamicSharedMemorySize, S256);
    cudaFuncSetAttribute(mma_gemm<256,1,1,1>, cudaFuncAttributeMaxDynamicSharedMemorySize, S256);
    cudaFuncSetAttribute(mma_gemm<256,0,1,1>, cudaFuncAttributeMaxDynamicSharedMemorySize, S256);
    cudaFuncSetAttribute(mma_gemm<256,0,0,2>, cudaFuncAttributeMaxDynamicSharedMemorySize, S256);
    cudaFuncSetAttribute(mma_gemm<128,1,1,1>, cudaFuncAttributeMaxDynamicSharedMemorySize, S128);
    cudaFuncSetAttribute(mma_gemm<128,0,1,1>, cudaFuncAttributeMaxDynamicSharedMemorySize, S128);

    const int MT = MM / BM;  // 250

    // launch 1: all prep fused
    prep_kernel<<<20113, 256>>>(targets, encoder_out, emb,
        W_enc, W_p1, W_p2, W_po, W_j1, W_j2, wt, encbf, embbf, features_len, out_lens);

    // launch 2: enc = encoder_out @ W_enc + b_enc  (fp32)
    mma_gemm<256,0,0,0><<<dim3(MT, 4), 256, S256>>>(
        encbf, wt + O_ENC, b_enc, enc, nullptr, nullptr, DENC, VV);

    // launch 3-4: a1 = tanh(gather @ W_p1 + b_p1)  (bf16)
    mma_gemm<128,1,1,1><<<dim3(MT, 1), 256, S128>>>(
        nullptr, wt + O_P1 + (size_t)512 * DENC, b_p1 + 512, hb1 + 512, nullptr, nullptr, DENC, PP);
    mma_gemm<256,1,1,1><<<dim3(MT, 2), 256, S256>>>(
        nullptr, wt + O_P1, b_p1, hb1, nullptr, nullptr, DENC, PP);

    // launch 5-6: a2 = tanh(a1 @ W_p2 + b_p2)  (bf16)   [launch 6 = ncu capture target]
    mma_gemm<128,0,1,1><<<dim3(MT, 1), 256, S128>>>(
        hb1, wt + O_P2 + (size_t)512 * PP, b_p2 + 512, hb2 + 512, nullptr, nullptr, PP, PP);
    mma_gemm<256,0,1,1><<<dim3(MT, 2), 256, S256>>>(
        hb1, wt + O_P2, b_p2, hb2, nullptr, nullptr, PP, PP);

    // launch 7: pred = a2 @ W_po + b_po (fp32); hsum = bf16(pred + enc)
    mma_gemm<256,0,0,2><<<dim3(MT, 4), 256, S256>>>(
        hb2, wt + O_PO, b_po, pred, enc, hsum, PP, VV);

    // launch 8-9: h = tanh(hsum @ W_j1 + b_j1)  (bf16)
    mma_gemm<128,0,1,1><<<dim3(MT, 1), 256, S128>>>(
        hsum, wt + O_J1 + (size_t)512 * VV, b_j1 + 512, hb1 + 512, nullptr, nullptr, VV, JJ);
    mma_gemm<256,0,1,1><<<dim3(MT, 2), 256, S256>>>(
        hsum, wt + O_J1, b_j1, hb1, nullptr, nullptr, VV, JJ);

    // launch 10: logits = h @ W_j2 + b_j2  (fp32)
    mma_gemm<256,0,0,0><<<dim3(MT, 4), 256, S256>>>(
        hb1, wt + O_J2, b_j2, logits, nullptr, nullptr, JJ, VV);

    // launch 11: merged log-softmaxes
    logsoftmax3<<<dim3(MM, 3), 256>>>(logits, pred, enc, out);
}

// round 9
// speedup vs baseline: 1.3706x; 1.0079x over previous
#include <cuda_runtime.h>
#include <cuda_bf16.h>
#include <math.h>
#include <stdint.h>

#if !defined(__CUDA_ARCH__) || defined(__CUDA_ARCH_FEAT_SM103_ALL) || \
    defined(__CUDA_ARCH_FEAT_SM100_ALL) || defined(__CUDA_ARCH_FEAT_SM101_ALL) || \
    defined(__CUDA_ARCH_FEAT_SM110_ALL)
#define HAS_TC 1
#else
#define HAS_TC 0
#endif

#define BB 16
#define TT 2000
#define MM (BB*TT)
#define DENC 512
#define VV 1024
#define EE 256
#define PP 640
#define JJ 640

#define BM 256            // 2 x 128 M-subtiles
#define BK 64
#define NS 3
#define NTHR 512

// ---------------- scratch ----------------
__device__ float g_enc[(size_t)MM * VV];
__device__ float g_pred[(size_t)MM * VV];
__device__ float g_logits[(size_t)MM * VV];
__device__ __nv_bfloat16 g_hsum[(size_t)MM * VV];
__device__ __nv_bfloat16 g_hb1[(size_t)MM * PP];
__device__ __nv_bfloat16 g_hb2[(size_t)MM * PP];
__device__ __nv_bfloat16 g_encbf[(size_t)MM * DENC];
__device__ __nv_bfloat16 g_embbf[(size_t)VV * EE];
__device__ __nv_bfloat16 g_wt[4u * 1024u * 1024u];
__device__ int2  g_ctx[MM];

#define O_ENC 0
#define O_P1  524288
#define O_P2  851968
#define O_PO  1261568
#define O_J1  1916928
#define O_J2  2572288

__device__ __forceinline__ uint32_t smem_u32(const void* p) {
    uint32_t a;
    asm("{ .reg .u64 t; cvta.to.shared.u64 t, %1; cvt.u32.u64 %0, t; }" : "=r"(a) : "l"(p));
    return a;
}
#define SWZ(b) ((b) ^ (((b) >> 3) & 0x70))

#if HAS_TC
__device__ __forceinline__ uint32_t elect1() {
    uint32_t p;
    asm volatile("{\n\t.reg .pred p;\n\telect.sync _|p, 0xFFFFFFFF;\n\tselp.b32 %0, 1, 0, p;\n\t}" : "=r"(p));
    return p;
}
__device__ __forceinline__ uint64_t make_desc(uint32_t addr) {
    return ((uint64_t)((addr >> 4) & 0x3FFF))
         | (1ull << 16) | (64ull << 32) | (1ull << 46) | (2ull << 61);
}
__device__ __forceinline__ void cp16(uint32_t s, const void* g) {
    asm volatile("cp.async.cg.shared.global [%0], [%1], 16;\n" :: "r"(s), "l"(g));
}
#define CP_COMMIT() asm volatile("cp.async.commit_group;\n" ::: "memory")

__device__ __forceinline__ void mbar_init(uint32_t a, uint32_t cnt) {
    asm volatile("mbarrier.init.shared.b64 [%0], %1;" :: "r"(a), "r"(cnt) : "memory");
}
__device__ __forceinline__ void mbar_wait(uint32_t a, uint32_t parity) {
    uint32_t done = 0;
    while (!done) {
        asm volatile("{\n\t.reg .pred p;\n\t"
            "mbarrier.try_wait.parity.acquire.cta.shared::cta.b64 p, [%1], %2, 0x989680;\n\t"
            "selp.b32 %0, 1, 0, p;\n\t}"
            : "=r"(done) : "r"(a), "r"(parity) : "memory");
    }
}
__device__ __forceinline__ void tc_alloc(uint32_t slot, uint32_t ncols) {
    asm volatile("tcgen05.alloc.cta_group::1.sync.aligned.shared::cta.b32 [%0], %1;"
                 :: "r"(slot), "r"(ncols) : "memory");
}
__device__ __forceinline__ void tc_dealloc(uint32_t tmem, uint32_t ncols) {
    asm volatile("tcgen05.dealloc.cta_group::1.sync.aligned.b32 %0, %1;" :: "r"(tmem), "r"(ncols));
}
__device__ __forceinline__ void tc_relinq() {
    asm volatile("tcgen05.relinquish_alloc_permit.cta_group::1.sync.aligned;");
}
__device__ __forceinline__ void tc_commit(uint32_t mbar) {
    asm volatile("tcgen05.commit.cta_group::1.mbarrier::arrive::one.shared::cluster.b64 [%0];"
                 :: "r"(mbar) : "memory");
}
__device__ __forceinline__ void mma_bf16_ss(uint32_t d, uint64_t ad, uint64_t bd,
                                            uint32_t idesc, uint32_t en) {
    asm volatile(
        "{\n\t.reg .pred p;\n\tsetp.ne.u32 p, %4, 0;\n\t"
        "tcgen05.mma.cta_group::1.kind::f16 [%0], %1, %2, %3, p;\n\t}"
        :: "r"(d), "l"(ad), "l"(bd), "r"(idesc), "r"(en) : "memory");
}
__device__ __forceinline__ void ldtm32(uint32_t* r, uint32_t a) {
    asm volatile(
        "tcgen05.ld.sync.aligned.32x32b.x32.b32 "
        "{%0, %1, %2, %3, %4, %5, %6, %7, %8, %9, %10, %11, %12, %13, %14, %15, "
        " %16, %17, %18, %19, %20, %21, %22, %23, %24, %25, %26, %27, %28, %29, %30, %31}, [%32];"
        : "=r"(r[0]), "=r"(r[1]), "=r"(r[2]), "=r"(r[3]), "=r"(r[4]), "=r"(r[5]), "=r"(r[6]), "=r"(r[7]),
          "=r"(r[8]), "=r"(r[9]), "=r"(r[10]), "=r"(r[11]), "=r"(r[12]), "=r"(r[13]), "=r"(r[14]), "=r"(r[15]),
          "=r"(r[16]), "=r"(r[17]), "=r"(r[18]), "=r"(r[19]), "=r"(r[20]), "=r"(r[21]), "=r"(r[22]), "=r"(r[23]),
          "=r"(r[24]), "=r"(r[25]), "=r"(r[26]), "=r"(r[27]), "=r"(r[28]), "=r"(r[29]), "=r"(r[30]), "=r"(r[31])
        : "r"(a));
}
#define TC_WAIT_LD()  asm volatile("tcgen05.wait::ld.sync.aligned;" ::: "memory")
#define TC_FENCE_AFTER()  asm volatile("tcgen05.fence::after_thread_sync;" ::: "memory")
#define TC_FENCE_BEFORE() asm volatile("tcgen05.fence::before_thread_sync;" ::: "memory")
#endif  // HAS_TC

// ---------------- fused prep: ctx + lens + f2bf(emb) + transpose + f2bf(enc) ----------------
__global__ __launch_bounds__(256) void prep_kernel(
    const int* __restrict__ targets, const float* __restrict__ encoder_out,
    const float* __restrict__ emb,
    const float* __restrict__ W0, const float* __restrict__ W1, const float* __restrict__ W2,
    const float* __restrict__ W3, const float* __restrict__ W4, const float* __restrict__ W5,
    __nv_bfloat16* __restrict__ wt, __nv_bfloat16* __restrict__ encbf,
    __nv_bfloat16* __restrict__ embbf,
    const int* __restrict__ flen, float* __restrict__ out_lens)
{
    __shared__ int pmax[2048];
    __shared__ int tot[256];
    __shared__ float tile[32][33];
    const int blk = blockIdx.x;
    const int tid = threadIdx.x;

    if (blk < 16) {
        const int* tg = targets + (size_t)blk * TT;
        int loc[8];
        int run = -1;
        #pragma unroll
        for (int j = 0; j < 8; ++j) {
            int t = tid * 8 + j;
            int p = (t < TT && tg[t] != 0) ? t : -1;
            run = max(run, p);
            loc[j] = run;
        }
        tot[tid] = run;
        __syncthreads();
        if (tid == 0) {
            int r = -1;
            for (int i = 0; i < 256; ++i) { int v = tot[i]; tot[i] = r; r = max(r, v); }
        }
        __syncthreads();
        int off = tot[tid];
        #pragma unroll
        for (int j = 0; j < 8; ++j) pmax[tid * 8 + j] = max(off, loc[j]);
        __syncthreads();
        for (int t = tid; t < TT; t += 256) {
            int p1 = (t >= 1) ? pmax[t - 1] : -1;
            int p2 = (t >= 2) ? pmax[t - 2] : -1;
            g_ctx[(size_t)blk * TT + t] = make_int2(p1 >= 0 ? tg[p1] : 0, p2 >= 0 ? tg[p2] : 0);
        }
    } else if (blk == 16) {
        if (tid < BB) out_lens[tid] = (float)flen[tid];
    } else if (blk < 273) {
        int i = (blk - 17) * 256 + tid;
        float4 v = reinterpret_cast<const float4*>(emb)[i];
        reinterpret_cast<__nv_bfloat162*>(embbf)[i * 2]     = __floats2bfloat162_rn(v.x, v.y);
        reinterpret_cast<__nv_bfloat162*>(embbf)[i * 2 + 1] = __floats2bfloat162_rn(v.z, v.w);
    } else if (blk < 4113) {
        int t = blk - 273;
        int wsel = t / 640, tidx = t % 640;
        const float* W; __nv_bfloat16* Wt; int K, N;
        switch (wsel) {
            case 0:  W = W0; Wt = wt + O_ENC; K = DENC; N = VV; break;
            case 1:  W = W1; Wt = wt + O_P1;  K = DENC; N = PP; break;
            case 2:  W = W2; Wt = wt + O_P2;  K = PP;   N = PP; break;
            case 3:  W = W3; Wt = wt + O_PO;  K = PP;   N = VV; break;
            case 4:  W = W4; Wt = wt + O_J1;  K = VV;   N = JJ; break;
            default: W = W5; Wt = wt + O_J2;  K = JJ;   N = VV; break;
        }
        int tn = N / 32;
        if (tidx < tn * (K / 32)) {
            int n0 = (tidx % tn) * 32, k0 = (tidx / tn) * 32;
            int tx = tid & 31, ty = tid >> 5;
            #pragma unroll
            for (int i = 0; i < 32; i += 8)
                tile[ty + i][tx] = W[(size_t)(k0 + ty + i) * N + n0 + tx];
            __syncthreads();
            #pragma unroll
            for (int i = 0; i < 32; i += 8)
                Wt[(size_t)(n0 + ty + i) * K + k0 + tx] = __float2bfloat16(tile[tx][ty + i]);
        }
    } else {
        int i = (blk - 4113) * 256 + tid;
        float4 v = reinterpret_cast<const float4*>(encoder_out)[i];
        reinterpret_cast<__nv_bfloat162*>(encbf)[i * 2]     = __floats2bfloat162_rn(v.x, v.y);
        reinterpret_cast<__nv_bfloat162*>(encbf)[i * 2 + 1] = __floats2bfloat162_rn(v.z, v.w);
    }
}

// ---------------- tcgen05 bf16 GEMM: BM=256 (2 subtiles), BN cols, 512 threads ----------------
// C = act(A @ Bt^T + bias). Bt [N,K] bf16.
// ASRC: 0 = A[M,K] bf16; 1 = gather from g_embbf via g_ctx.
// OUTMODE: 0 = fp32 C; 1 = bf16 C; 2 = fp32 C + bf16 Csum = C + Cadd(fp32).
template<int BN, int ASRC, int ACT, int OUTMODE>
__global__ __launch_bounds__(NTHR) void mma_gemm(
    const __nv_bfloat16* __restrict__ A, const __nv_bfloat16* __restrict__ Bt,
    const float* __restrict__ bias,
    void* __restrict__ Cv, const float* __restrict__ Cadd, __nv_bfloat16* __restrict__ Csum,
    int K, int ldc)
{
#if HAS_TC
    extern __shared__ char smem[];
    const uint32_t sbase = smem_u32(smem);
    const int tid = threadIdx.x;
    const int wid = tid >> 5;
    const int lane = tid & 31;
    const int gRow = blockIdx.x * BM;
    const int ncol0 = blockIdx.y * BN;
    const __nv_bfloat16* BtT = Bt + (size_t)ncol0 * K;

    const uint32_t ctrl = sbase;
    const uint32_t mb   = sbase + 16;
    const uint32_t tile0 = (sbase + 1024 + 1023) & ~1023u;
    const int STAGE = (BM + BN) * BK * 2;          // 64KB (BN=256) / 48KB (BN=128)

    if (wid == 0) tc_alloc(ctrl, 512);
    if (tid == 0) { for (int s = 0; s < NS; s++) mbar_init(mb + 8 * s, 1); }
    __syncthreads();
    uint32_t tmem;
    asm volatile("ld.shared.b32 %0, [%1];" : "=r"(tmem) : "r"(ctrl));

    const int KT = K / BK;

    auto load_stage = [&](int ki, int s) {
        const int k0 = ki * BK;
        const uint32_t ab = tile0 + s * STAGE;          // A: 256 rows (subtile0 then 1)
        const uint32_t bb = ab + BM * BK * 2;           // B: BN rows
        #pragma unroll
        for (int t = 0; t < 4; t++) {                   // 2048 cp16 for A
            int q = tid + t * NTHR, r = q >> 3, cv = q & 7;
            const __nv_bfloat16* gp;
            if (ASRC == 1) {
                int2 cx = g_ctx[gRow + r];
                int idx = (k0 < 256) ? cx.x : cx.y;
                gp = g_embbf + (size_t)idx * EE + ((k0 & 255) + cv * 8);
            } else {
                gp = A + (size_t)(gRow + r) * K + (k0 + cv * 8);
            }
            cp16(ab + SWZ(r * 128 + cv * 16), gp);
        }
        #pragma unroll
        for (int t = 0; t < BN / 64; t++) {             // BN*8 cp16 for B
            int q = tid + t * NTHR, r = q >> 3, cv = q & 7;
            cp16(bb + SWZ(r * 128 + cv * 16), BtT + (size_t)r * K + (k0 + cv * 8));
        }
    };

    load_stage(0, 0); CP_COMMIT();
    load_stage(1, 1); CP_COMMIT();

    const uint32_t idesc = (1u << 4) | (1u << 7) | (1u << 10)
                         | ((uint32_t)(BN / 8) << 17) | (8u << 24);   // M=128 per subtile

    for (int i = 0; i < KT; i++) {
        const int s = i % NS;
        asm volatile("cp.async.wait_group 1;\n" ::: "memory");
        __syncthreads();
        if (wid == 0) {
            asm volatile("fence.proxy.async.shared::cta;" ::: "memory");
            TC_FENCE_AFTER();
            if (elect1()) {
                const uint32_t ab = tile0 + s * STAGE;
                const uint32_t bb = ab + BM * BK * 2;
                uint64_t bd = make_desc(bb);
                #pragma unroll
                for (int m = 0; m < 2; m++) {           // 2 M-subtiles share B
                    uint64_t ad = make_desc(ab + m * (128 * 128));
                    #pragma unroll
                    for (int kk = 0; kk < 4; kk++)
                        mma_bf16_ss(tmem + m * 256, ad + kk * 2, bd + kk * 2, idesc,
                                    (i | kk) ? 1u : 0u);
                }
                tc_commit(mb + 8 * s);
            }
        }
        if (i + 2 < KT) {
            if (i >= 1) mbar_wait(mb + 8 * ((i - 1) % NS), ((i - 1) / NS) & 1);
            load_stage(i + 2, (i + 2) % NS);
        }
        CP_COMMIT();
    }
    mbar_wait(mb + 8 * ((KT - 1) % NS), ((KT - 1) / NS) & 1);
    TC_FENCE_AFTER();
    __syncthreads();

    // ---- epilogue: warps 0-3 drain subtile0, warps 4-7 subtile1 ----
    if (wid < 8) {
        const int mt = wid >> 2;                        // subtile
        const int row = gRow + mt * 128 + (wid & 3) * 32 + lane;
        const uint32_t tbase = tmem + mt * 256;
        const float* bs = bias + ncol0;
        float* crowf = (OUTMODE != 1) ? ((float*)Cv + (size_t)row * ldc + ncol0) : nullptr;
        __nv_bfloat16* crowh = (OUTMODE == 1) ? ((__nv_bfloat16*)Cv + (size_t)row * ldc + ncol0) : nullptr;
        const float* erow = (OUTMODE == 2) ? (Cadd + (size_t)row * ldc + ncol0) : nullptr;
        __nv_bfloat16* srow = (OUTMODE == 2) ? (Csum + (size_t)row * ldc + ncol0) : nullptr;
        #pragma unroll
        for (int c0 = 0; c0 < BN; c0 += 32) {
            uint32_t r[32];
            ldtm32(r, tbase + c0);
            TC_WAIT_LD();
            #pragma unroll
            for (int j = 0; j < 32; j += 4) {
                float4 b4 = *reinterpret_cast<const float4*>(bs + c0 + j);
                float4 o;
                o.x = __uint_as_float(r[j + 0]) + b4.x;
                o.y = __uint_as_float(r[j + 1]) + b4.y;
                o.z = __uint_as_float(r[j + 2]) + b4.z;
                o.w = __uint_as_float(r[j + 3]) + b4.w;
                if (ACT) { o.x = tanhf(o.x); o.y = tanhf(o.y); o.z = tanhf(o.z); o.w = tanhf(o.w); }
                if (OUTMODE == 1) {
                    reinterpret_cast<__nv_bfloat162*>(crowh + c0 + j)[0] = __floats2bfloat162_rn(o.x, o.y);
                    reinterpret_cast<__nv_bfloat162*>(crowh + c0 + j)[1] = __floats2bfloat162_rn(o.z, o.w);
                } else {
                    *reinterpret_cast<float4*>(crowf + c0 + j) = o;
                    if (OUTMODE == 2) {
                        float4 e4 = *reinterpret_cast<const float4*>(erow + c0 + j);
                        reinterpret_cast<__nv_bfloat162*>(srow + c0 + j)[0] = __floats2bfloat162_rn(o.x + e4.x, o.y + e4.y);
                        reinterpret_cast<__nv_bfloat162*>(srow + c0 + j)[1] = __floats2bfloat162_rn(o.z + e4.z, o.w + e4.w);
                    }
                }
            }
        }
        TC_FENCE_BEFORE();
    }
    __syncthreads();
    if (wid == 0) {
        tc_relinq();
        tc_dealloc(tmem, 512);
    }
#else
    // ======== SIMT fallback (compute_103 PTX pass; never selected at runtime) ========
    const int tid = threadIdx.x;
    const int gRow = blockIdx.x * BM;
    const int ncol0 = blockIdx.y * BN;
    for (int idx = tid; idx < BM * BN; idx += NTHR) {
        int r = idx / BN, n = idx % BN;
        int row = gRow + r, col = ncol0 + n;
        float acc = 0.f;
        int2 cx = g_ctx[row];
        for (int k = 0; k < K; k++) {
            float a;
            if (ASRC == 1) {
                int e = (k < 256) ? cx.x : cx.y;
                a = __bfloat162float(g_embbf[(size_t)e * EE + (k & 255)]);
            } else a = __bfloat162float(A[(size_t)row * K + k]);
            acc += a * __bfloat162float(Bt[(size_t)col * K + k]);
        }
        acc += bias[col];
        if (ACT) acc = tanhf(acc);
        if (OUTMODE == 1) {
            ((__nv_bfloat16*)Cv)[(size_t)row * ldc + col] = __float2bfloat16(acc);
        } else {
            ((float*)Cv)[(size_t)row * ldc + col] = acc;
            if (OUTMODE == 2)
                Csum[(size_t)row * ldc + col] =
                    __float2bfloat16(acc + Cadd[(size_t)row * ldc + col]);
        }
    }
#endif
}

// ---------------- merged log-softmax (3 tensors) ----------------
__global__ __launch_bounds__(256) void logsoftmax3(
    const float* __restrict__ lg, const float* __restrict__ pd,
    const float* __restrict__ en, float* __restrict__ out)
{
    __shared__ float redm[8];
    __shared__ float reds[8];
    int row = blockIdx.x;
    const float* X; float* Y;
    if (blockIdx.y == 0)      { X = lg; Y = out; }
    else if (blockIdx.y == 1) { X = pd; Y = out + (size_t)MM * VV; }
    else                      { X = en; Y = out + 2 * (size_t)MM * VV; }
    int tid = threadIdx.x;
    float4 x = reinterpret_cast<const float4*>(X + (size_t)row * VV)[tid];
    float m = fmaxf(fmaxf(x.x, x.y), fmaxf(x.z, x.w));
    #pragma unroll
    for (int o = 16; o; o >>= 1) m = fmaxf(m, __shfl_xor_sync(0xffffffffu, m, o));
    if ((tid & 31) == 0) redm[tid >> 5] = m;
    __syncthreads();
    float mx = redm[0];
    #pragma unroll
    for (int i = 1; i < 8; ++i) mx = fmaxf(mx, redm[i]);
    float s = expf(x.x - mx) + expf(x.y - mx) + expf(x.z - mx) + expf(x.w - mx);
    #pragma unroll
    for (int o = 16; o; o >>= 1) s += __shfl_xor_sync(0xffffffffu, s, o);
    if ((tid & 31) == 0) reds[tid >> 5] = s;
    __syncthreads();
    float sum = 0.f;
    #pragma unroll
    for (int i = 0; i < 8; ++i) sum += reds[i];
    float lse = mx + logf(sum);
    float4 y = make_float4(x.x - lse, x.y - lse, x.z - lse, x.w - lse);
    reinterpret_cast<float4*>(Y + (size_t)row * VV)[tid] = y;
}

// ---------------- launch ----------------
extern "C" void kernel_launch(void* const* d_in, const int* in_sizes, int n_in,
                              void* d_out, int out_size)
{
    const float* encoder_out  = (const float*)d_in[0];
    const int*   features_len = (const int*)  d_in[1];
    const int*   targets      = (const int*)  d_in[2];
    const float* W_enc = (const float*)d_in[3];
    const float* b_enc = (const float*)d_in[4];
    const float* emb   = (const float*)d_in[5];
    const float* W_p1  = (const float*)d_in[6];
    const float* b_p1  = (const float*)d_in[7];
    const float* W_p2  = (const float*)d_in[8];
    const float* b_p2  = (const float*)d_in[9];
    const float* W_po  = (const float*)d_in[10];
    const float* b_po  = (const float*)d_in[11];
    const float* W_j1  = (const float*)d_in[12];
    const float* b_j1  = (const float*)d_in[13];
    const float* W_j2  = (const float*)d_in[14];
    const float* b_j2  = (const float*)d_in[15];

    float *enc, *pred, *logits;
    __nv_bfloat16 *hsum, *hb1, *hb2, *encbf, *embbf, *wt;
    cudaGetSymbolAddress((void**)&enc,    g_enc);
    cudaGetSymbolAddress((void**)&pred,   g_pred);
    cudaGetSymbolAddress((void**)&logits, g_logits);
    cudaGetSymbolAddress((void**)&hsum,   g_hsum);
    cudaGetSymbolAddress((void**)&hb1,    g_hb1);
    cudaGetSymbolAddress((void**)&hb2,    g_hb2);
    cudaGetSymbolAddress((void**)&encbf,  g_encbf);
    cudaGetSymbolAddress((void**)&embbf,  g_embbf);
    cudaGetSymbolAddress((void**)&wt,     g_wt);

    float* out = (float*)d_out;
    float* out_lens = out + 3 * (size_t)MM * VV;

    const int S256 = 2048 + NS * (BM + 256) * BK * 2;   // 198656
    const int S128 = 2048 + NS * (BM + 128) * BK * 2;   // 149504
    cudaFuncSetAttribute(mma_gemm<256,0,0,0>, cudaFuncAttributeMaxDynamicSharedMemorySize, S256);
    cudaFuncSetAttribute(mma_gemm<256,1,1,1>, cudaFuncAttributeMaxDynamicSharedMemorySize, S256);
    cudaFuncSetAttribute(mma_gemm<256,0,1,1>, cudaFuncAttributeMaxDynamicSharedMemorySize, S256);
    cudaFuncSetAttribute(mma_gemm<256,0,0,2>, cudaFuncAttributeMaxDynamicSharedMemorySize, S256);
    cudaFuncSetAttribute(mma_gemm<128,1,1,1>, cudaFuncAttributeMaxDynamicSharedMemorySize, S128);
    cudaFuncSetAttribute(mma_gemm<128,0,1,1>, cudaFuncAttributeMaxDynamicSharedMemorySize, S128);

    const int MT = MM / BM;  // 125

    // launch 1: all prep fused
    prep_kernel<<<20113, 256>>>(targets, encoder_out, emb,
        W_enc, W_p1, W_p2, W_po, W_j1, W_j2, wt, encbf, embbf, features_len, out_lens);

    // launch 2: enc = encoder_out @ W_enc + b_enc  (fp32)
    mma_gemm<256,0,0,0><<<dim3(MT, 4), NTHR, S256>>>(
        encbf, wt + O_ENC, b_enc, enc, nullptr, nullptr, DENC, VV);

    // launch 3-4: a1 = tanh(gather @ W_p1 + b_p1)  (bf16)
    mma_gemm<128,1,1,1><<<dim3(MT, 1), NTHR, S128>>>(
        nullptr, wt + O_P1 + (size_t)512 * DENC, b_p1 + 512, hb1 + 512, nullptr, nullptr, DENC, PP);
    mma_gemm<256,1,1,1><<<dim3(MT, 2), NTHR, S256>>>(
        nullptr, wt + O_P1, b_p1, hb1, nullptr, nullptr, DENC, PP);

    // launch 5-6: a2 = tanh(a1 @ W_p2 + b_p2)  (bf16)   [launch 6 = ncu capture target]
    mma_gemm<128,0,1,1><<<dim3(MT, 1), NTHR, S128>>>(
        hb1, wt + O_P2 + (size_t)512 * PP, b_p2 + 512, hb2 + 512, nullptr, nullptr, PP, PP);
    mma_gemm<256,0,1,1><<<dim3(MT, 2), NTHR, S256>>>(
        hb1, wt + O_P2, b_p2, hb2, nullptr, nullptr, PP, PP);

    // launch 7: pred = a2 @ W_po + b_po (fp32); hsum = bf16(pred + enc)
    mma_gemm<256,0,0,2><<<dim3(MT, 4), NTHR, S256>>>(
        hb2, wt + O_PO, b_po, pred, enc, hsum, PP, VV);

    // launch 8-9: h = tanh(hsum @ W_j1 + b_j1)  (bf16)
    mma_gemm<128,0,1,1><<<dim3(MT, 1), NTHR, S128>>>(
        hsum, wt + O_J1 + (size_t)512 * VV, b_j1 + 512, hb1 + 512, nullptr, nullptr, VV, JJ);
    mma_gemm<256,0,1,1><<<dim3(MT, 2), NTHR, S256>>>(
        hsum, wt + O_J1, b_j1, hb1, nullptr, nullptr, VV, JJ);

    // launch 10: logits = h @ W_j2 + b_j2  (fp32)
    mma_gemm<256,0,0,0><<<dim3(MT, 4), NTHR, S256>>>(
        hb1, wt + O_J2, b_j2, logits, nullptr, nullptr, JJ, VV);

    // launch 11: merged log-softmaxes
    logsoftmax3<<<dim3(MM, 3), 256>>>(logits, pred, enc, out);
}